// round 3
// baseline (speedup 1.0000x reference)
#include <cuda_runtime.h>
#include <cuda_bf16.h>
#include <cstdint>

#define NTH 256
#define BP  128

// Combined channel-last bf16 grids: levels S=16,32,64,96, 32 channels each
// voxel offsets: 0, 4096, 36864, 299008 ; total 1183744 voxels
#define TOT_VOX 1183744
__device__ __nv_bfloat16 g_comb[(size_t)TOT_VOX * 32];

// ---------------------------------------------------------------------------
// Prolog: (C,S,S,S) fp32 vec+tau -> channel-last bf16 combined
// ---------------------------------------------------------------------------
__global__ void transpose_level(const float* __restrict__ vec,
                                const float* __restrict__ tau,
                                int vol, long long outBase)
{
    __shared__ float tile[32][257];
    const int vbase = blockIdx.x * 256;
    const int tid = threadIdx.x;
    for (int i = tid; i < 32 * 256; i += NTH) {
        int ch = i >> 8, vl = i & 255, v = vbase + vl;
        float val = 0.f;
        if (v < vol)
            val = (ch < 16) ? vec[(size_t)ch * vol + v]
                            : tau[(size_t)(ch - 16) * vol + v];
        tile[ch][vl] = val;
    }
    __syncthreads();
    __nv_bfloat16* out = g_comb + outBase;
    for (int i = tid; i < 16 * 256; i += NTH) {
        int vl = i >> 4, cp = i & 15, v = vbase + vl;
        if (v < vol) {
            __nv_bfloat162 val = __floats2bfloat162_rn(tile[2 * cp][vl], tile[2 * cp + 1][vl]);
            *reinterpret_cast<__nv_bfloat162*>(out + (size_t)v * 32 + 2 * cp) = val;
        }
    }
}

// ---------------------------------------------------------------------------
// Math helpers
// ---------------------------------------------------------------------------
__device__ __forceinline__ float silu_f(float x) {
    return x * __fdividef(1.f, 1.f + __expf(-x));
}
__device__ __forceinline__ float tanh_f(float x) {
    float ax = fabsf(x);
    if (ax < 0.25f) {
        float x2 = x * x;
        return x * (1.f + x2 * (-0.333333333f + x2 * (0.133333333f - 0.0539682540f * x2)));
    }
    float e = __expf(2.f * x);
    return 1.f - __fdividef(2.f, e + 1.f);
}

__device__ __forceinline__ void accum8(float* acc, uint4 q, float w) {
    float2 f;
    f = __bfloat1622float2(*reinterpret_cast<__nv_bfloat162*>(&q.x));
    acc[0] = fmaf(w, f.x, acc[0]); acc[1] = fmaf(w, f.y, acc[1]);
    f = __bfloat1622float2(*reinterpret_cast<__nv_bfloat162*>(&q.y));
    acc[2] = fmaf(w, f.x, acc[2]); acc[3] = fmaf(w, f.y, acc[3]);
    f = __bfloat1622float2(*reinterpret_cast<__nv_bfloat162*>(&q.z));
    acc[4] = fmaf(w, f.x, acc[4]); acc[5] = fmaf(w, f.y, acc[5]);
    f = __bfloat1622float2(*reinterpret_cast<__nv_bfloat162*>(&q.w));
    acc[6] = fmaf(w, f.x, acc[6]); acc[7] = fmaf(w, f.y, acc[7]);
}

// Trilinear sample of one level (16 vec + 16 tau channels), silu applied,
// writes bf16 features at sA[p*136 + chBase + c] / sT[...]
template<int S>
__device__ __forceinline__ void sample_level(int chBase, long long voxOff,
                                             float cx, float cy, float cz, int p,
                                             __nv_bfloat16* sA, __nv_bfloat16* sT)
{
    const float s1 = (float)(S - 1);
    float px = fminf(fmaxf((cx + 1.f) * 0.5f * s1, 0.f), s1);
    float py = fminf(fmaxf((cy + 1.f) * 0.5f * s1, 0.f), s1);
    float pz = fminf(fmaxf((cz + 1.f) * 0.5f * s1, 0.f), s1);
    int x0 = (int)px, y0 = (int)py, z0 = (int)pz;
    float wx = px - (float)x0, wy = py - (float)y0, wz = pz - (float)z0;
    int x1 = min(x0 + 1, S - 1), y1 = min(y0 + 1, S - 1), z1 = min(z0 + 1, S - 1);

    const __nv_bfloat16* g = g_comb + voxOff * 32;
    float acc[32];
#pragma unroll
    for (int i = 0; i < 32; i++) acc[i] = 0.f;

    const int   xs[2]  = {x0, x1}, ys[2] = {y0, y1}, zs[2] = {z0, z1};
    const float wxs[2] = {1.f - wx, wx}, wys[2] = {1.f - wy, wy}, wzs[2] = {1.f - wz, wz};
#pragma unroll
    for (int a = 0; a < 2; a++)
#pragma unroll
        for (int b = 0; b < 2; b++)
#pragma unroll
            for (int c = 0; c < 2; c++) {
                float w = wzs[a] * wys[b] * wxs[c];
                const uint4* q = reinterpret_cast<const uint4*>(
                    g + (size_t)((zs[a] * S + ys[b]) * S + xs[c]) * 32);
                uint4 q0 = q[0], q1 = q[1], q2 = q[2], q3 = q[3];
                accum8(acc + 0,  q0, w);
                accum8(acc + 8,  q1, w);
                accum8(acc + 16, q2, w);
                accum8(acc + 24, q3, w);
            }
#pragma unroll
    for (int c = 0; c < 16; c += 2) {
        *reinterpret_cast<__nv_bfloat162*>(&sA[p * 136 + chBase + c]) =
            __floats2bfloat162_rn(silu_f(acc[c]), silu_f(acc[c + 1]));
        *reinterpret_cast<__nv_bfloat162*>(&sT[p * 136 + chBase + c]) =
            __floats2bfloat162_rn(silu_f(acc[16 + c]), silu_f(acc[16 + c + 1]));
    }
}

// Cooperative fp32 -> bf16 weight load into smem (row stride 136 bf16)
__device__ __forceinline__ void load_w(const float* __restrict__ W, __nv_bfloat16* sW)
{
    const int tid = threadIdx.x;
#pragma unroll 4
    for (int i = tid; i < 128 * 32; i += NTH) {
        int r = i >> 5, c4 = (i & 31) * 4;
        float4 f = *reinterpret_cast<const float4*>(W + r * 128 + c4);
        *reinterpret_cast<__nv_bfloat162*>(sW + r * 136 + c4)     = __floats2bfloat162_rn(f.x, f.y);
        *reinterpret_cast<__nv_bfloat162*>(sW + r * 136 + c4 + 2) = __floats2bfloat162_rn(f.z, f.w);
    }
}

// ---------------------------------------------------------------------------
// mma.sync helpers
// ---------------------------------------------------------------------------
__device__ __forceinline__ void ldm4(uint32_t& r0, uint32_t& r1, uint32_t& r2, uint32_t& r3,
                                     uint32_t addr)
{
    asm volatile("ldmatrix.sync.aligned.m8n8.x4.shared.b16 {%0,%1,%2,%3}, [%4];\n"
                 : "=r"(r0), "=r"(r1), "=r"(r2), "=r"(r3) : "r"(addr));
}
__device__ __forceinline__ void mma16816(float* c, const uint32_t* a, const uint32_t* b)
{
    asm volatile(
        "mma.sync.aligned.m16n8k16.row.col.f32.bf16.bf16.f32 "
        "{%0,%1,%2,%3},{%4,%5,%6,%7},{%8,%9},{%0,%1,%2,%3};\n"
        : "+f"(c[0]), "+f"(c[1]), "+f"(c[2]), "+f"(c[3])
        : "r"(a[0]), "r"(a[1]), "r"(a[2]), "r"(a[3]), "r"(b[0]), "r"(b[1]));
}

// C[p][j] = sum_k A[p][k] * W[j][k], 128x128x128, bf16 in / fp32 acc.
// 8 warps: warp tile 32(m) x 64(n); frag grid 2 x 8 of m16n8k16.
__device__ __forceinline__ void gemm128(const __nv_bfloat16* A, const __nv_bfloat16* W,
                                        float (&acc)[2][8][4], int lane, int m0, int n0)
{
#pragma unroll
    for (int mi = 0; mi < 2; mi++)
#pragma unroll
        for (int ni = 0; ni < 8; ni++)
#pragma unroll
            for (int t = 0; t < 4; t++) acc[mi][ni][t] = 0.f;

    uint32_t aBase = (uint32_t)__cvta_generic_to_shared(A)
                   + (uint32_t)((m0 + (lane & 15)) * 272 + (lane >> 4) * 16);
    uint32_t bBase = (uint32_t)__cvta_generic_to_shared(W)
                   + (uint32_t)((n0 + (lane & 7) + ((lane >> 4) << 3)) * 272
                                + ((lane >> 3) & 1) * 16);
#pragma unroll 2
    for (int k = 0; k < 8; k++) {
        uint32_t a[2][4];
        ldm4(a[0][0], a[0][1], a[0][2], a[0][3], aBase + k * 32);
        ldm4(a[1][0], a[1][1], a[1][2], a[1][3], aBase + 16 * 272 + k * 32);
        uint32_t b[8][2];
#pragma unroll
        for (int t = 0; t < 4; t++) {
            uint32_t r0, r1, r2, r3;
            ldm4(r0, r1, r2, r3, bBase + t * (16 * 272) + k * 32);
            b[2 * t][0] = r0; b[2 * t][1] = r1;
            b[2 * t + 1][0] = r2; b[2 * t + 1][1] = r3;
        }
#pragma unroll
        for (int mi = 0; mi < 2; mi++)
#pragma unroll
            for (int ni = 0; ni < 8; ni++)
                mma16816(acc[mi][ni], a[mi], b[ni]);
    }
}

// ---------------------------------------------------------------------------
// Fused main kernel: 128 points per block
// ---------------------------------------------------------------------------
__global__ void __launch_bounds__(NTH, 1)
fused_kernel(const float* __restrict__ phys, const float* __restrict__ net,
             const float* __restrict__ tauIn,
             const float* __restrict__ vec_pe_w, const float* __restrict__ tau_pe_w,
             const float* __restrict__ tau_pe_b, const float* __restrict__ vec_scale,
             const float* __restrict__ vec_map_w, const float* __restrict__ tau_mlp_w,
             const float* __restrict__ vec_mlp_w, const float* __restrict__ tau_params,
             const float* __restrict__ last_w, float* __restrict__ outG)
{
    extern __shared__ char smem[];
    __nv_bfloat16* sA0 = (__nv_bfloat16*)(smem);            // 34816 B
    __nv_bfloat16* sA1 = (__nv_bfloat16*)(smem + 34816);    // 34816 B
    __nv_bfloat16* sT  = (__nv_bfloat16*)(smem + 69632);    // 34816 B
    __nv_bfloat16* sW  = (__nv_bfloat16*)(smem + 104448);   // 34816 B
    float* sTau   = (float*)(smem + 139264);                // 512 B
    float* sScale = (float*)(smem + 139776);                // 512 B
    float* sCx    = (float*)(smem + 140288);
    float* sCy    = (float*)(smem + 140800);
    float* sCz    = (float*)(smem + 141312);                // end 141824
    float* sOutF  = (float*)(smem);                          // 128*132*4 = 67584 (reuse)

    const int tid = threadIdx.x;
    const int p0  = blockIdx.x * BP;

    if (tid < BP) {
        int gp = p0 + tid;
        sCx[tid]  = net[gp * 3 + 0];
        sCy[tid]  = net[gp * 3 + 1];
        sCz[tid]  = net[gp * 3 + 2];
        sTau[tid] = tauIn[gp];
        sScale[tid] = vec_scale[tid];
    }
    __syncthreads();

    // ---- sampling + FFM ----
    {
        int p = tid & 127, grp = tid >> 7;
        float cx = sCx[p], cy = sCy[p], cz = sCz[p];
        if (grp == 0) {
            sample_level<16>(0,  0LL,      cx, cy, cz, p, sA0, sT);
            sample_level<32>(16, 4096LL,   cx, cy, cz, p, sA0, sT);
            const float* w = vec_pe_w;
#pragma unroll 4
            for (int j = 0; j < 64; j++) {
                float d = cx * w[j * 3] + cy * w[j * 3 + 1] + cz * w[j * 3 + 2];
                sA0[p * 136 + 64 + j] = __float2bfloat16(__sinf(d));
            }
        } else {
            sample_level<64>(32, 36864LL,  cx, cy, cz, p, sA0, sT);
            sample_level<96>(48, 299008LL, cx, cy, cz, p, sA0, sT);
            const float* w = tau_pe_w;
#pragma unroll 4
            for (int j = 0; j < 64; j++) {
                float d = cx * w[j * 3] + cy * w[j * 3 + 1] + cz * w[j * 3 + 2] + tau_pe_b[j];
                sT[p * 136 + 64 + j] = __float2bfloat16(__sinf(d));
            }
        }
    }
    __syncthreads();

    const int lane = tid & 31, wid = tid >> 5;
    const int m0 = (wid & 3) * 32, n0 = (wid >> 2) * 64;
    float acc[2][8][4];
    float outF[2][8][4];

    // ---- vec_map layer 0 ----
    load_w(vec_map_w, sW);
    __syncthreads();
    gemm128(sA0, sW, acc, lane, m0, n0);
#pragma unroll
    for (int mi = 0; mi < 2; mi++)
#pragma unroll
        for (int ni = 0; ni < 8; ni++)
#pragma unroll
            for (int hi = 0; hi < 2; hi++) {
                int p = m0 + mi * 16 + (lane >> 2) + hi * 8;
                int j = n0 + ni * 8 + (lane & 3) * 2;
                *reinterpret_cast<__nv_bfloat162*>(&sA1[p * 136 + j]) =
                    __floats2bfloat162_rn(silu_f(acc[mi][ni][hi * 2]),
                                          silu_f(acc[mi][ni][hi * 2 + 1]));
            }
    __syncthreads();

    // ---- vec_map layer 1 + out init: out = tanh(tau*scale*silu(h)) ----
    load_w(vec_map_w + 128 * 128, sW);
    __syncthreads();
    gemm128(sA1, sW, acc, lane, m0, n0);
#pragma unroll
    for (int mi = 0; mi < 2; mi++)
#pragma unroll
        for (int ni = 0; ni < 8; ni++)
#pragma unroll
            for (int hi = 0; hi < 2; hi++) {
                int p = m0 + mi * 16 + (lane >> 2) + hi * 8;
                int j = n0 + ni * 8 + (lane & 3) * 2;
                float tp = sTau[p];
                float s0 = sScale[j], s1 = sScale[j + 1];
                float o0 = tanh_f(tp * s0 * silu_f(acc[mi][ni][hi * 2]));
                float o1 = tanh_f(tp * s1 * silu_f(acc[mi][ni][hi * 2 + 1]));
                outF[mi][ni][hi * 2]     = o0;
                outF[mi][ni][hi * 2 + 1] = o1;
                *reinterpret_cast<__nv_bfloat162*>(&sA0[p * 136 + j]) =
                    __floats2bfloat162_rn(o0, o1);
            }
    __syncthreads();

    // ---- tau path: ttt = tauF @ tau_mlp_w^T (stored bf16 into sT) ----
    load_w(tau_mlp_w, sW);
    __syncthreads();
    gemm128(sT, sW, acc, lane, m0, n0);
    __syncthreads();
#pragma unroll
    for (int mi = 0; mi < 2; mi++)
#pragma unroll
        for (int ni = 0; ni < 8; ni++)
#pragma unroll
            for (int hi = 0; hi < 2; hi++) {
                int p = m0 + mi * 16 + (lane >> 2) + hi * 8;
                int j = n0 + ni * 8 + (lane & 3) * 2;
                *reinterpret_cast<__nv_bfloat162*>(&sT[p * 136 + j]) =
                    __floats2bfloat162_rn(acc[mi][ni][hi * 2], acc[mi][ni][hi * 2 + 1]);
            }
    __syncthreads();

    // ---- 3 residual layers ----
#pragma unroll 1
    for (int idx = 0; idx < 3; idx++) {
        load_w(vec_mlp_w + idx * 128 * 128, sW);
        __syncthreads();
        const __nv_bfloat16* Abuf = (idx & 1) ? sA1 : sA0;
        __nv_bfloat16*       Bout = (idx & 1) ? sA0 : sA1;
        gemm128(Abuf, sW, acc, lane, m0, n0);
        const float* tpar = tau_params + idx * 128;
#pragma unroll
        for (int mi = 0; mi < 2; mi++)
#pragma unroll
            for (int ni = 0; ni < 8; ni++)
#pragma unroll
                for (int hi = 0; hi < 2; hi++) {
                    int p = m0 + mi * 16 + (lane >> 2) + hi * 8;
                    int j = n0 + ni * 8 + (lane & 3) * 2;
                    float h0 = acc[mi][ni][hi * 2], h1 = acc[mi][ni][hi * 2 + 1];
                    if (idx == 0) {
                        float2 t = __bfloat1622float2(
                            *reinterpret_cast<__nv_bfloat162*>(&sT[p * 136 + j]));
                        h0 *= t.x; h1 *= t.y;
                    }
                    float tp = sTau[p];
                    float tt0 = tanh_f(tp * __ldg(&tpar[j]));
                    float tt1 = tanh_f(tp * __ldg(&tpar[j + 1]));
                    float o0 = outF[mi][ni][hi * 2]     + tt0 * silu_f(h0);
                    float o1 = outF[mi][ni][hi * 2 + 1] + tt1 * silu_f(h1);
                    outF[mi][ni][hi * 2]     = o0;
                    outF[mi][ni][hi * 2 + 1] = o1;
                    if (idx < 2)
                        *reinterpret_cast<__nv_bfloat162*>(&Bout[p * 136 + j]) =
                            __floats2bfloat162_rn(o0, o1);
                }
        __syncthreads();
    }

    // ---- spill fp32 out to smem (reuses sA0/sA1 region) ----
#pragma unroll
    for (int mi = 0; mi < 2; mi++)
#pragma unroll
        for (int ni = 0; ni < 8; ni++)
#pragma unroll
            for (int hi = 0; hi < 2; hi++) {
                int p = m0 + mi * 16 + (lane >> 2) + hi * 8;
                int j = n0 + ni * 8 + (lane & 3) * 2;
                *reinterpret_cast<float2*>(&sOutF[p * 132 + j]) =
                    make_float2(outF[mi][ni][hi * 2], outF[mi][ni][hi * 2 + 1]);
            }
    __syncthreads();

    // ---- head: res = phys + out @ last_w^T ----
    if (tid < BP) {
        int p = tid;
        float a0 = 0.f, a1 = 0.f, a2 = 0.f;
#pragma unroll 8
        for (int j = 0; j < 128; j += 4) {
            float4 o  = *reinterpret_cast<float4*>(&sOutF[p * 132 + j]);
            float4 w0 = __ldg(reinterpret_cast<const float4*>(last_w + j));
            float4 w1 = __ldg(reinterpret_cast<const float4*>(last_w + 128 + j));
            float4 w2 = __ldg(reinterpret_cast<const float4*>(last_w + 256 + j));
            a0 += o.x * w0.x + o.y * w0.y + o.z * w0.z + o.w * w0.w;
            a1 += o.x * w1.x + o.y * w1.y + o.z * w1.z + o.w * w1.w;
            a2 += o.x * w2.x + o.y * w2.y + o.z * w2.z + o.w * w2.w;
        }
        long long gp = (long long)(p0 + p) * 3;
        outG[gp + 0] = phys[gp + 0] + a0;
        outG[gp + 1] = phys[gp + 1] + a1;
        outG[gp + 2] = phys[gp + 2] + a2;
    }
}

// ---------------------------------------------------------------------------
extern "C" void kernel_launch(void* const* d_in, const int* in_sizes, int n_in,
                              void* d_out, int out_size)
{
    const float* phys      = (const float*)d_in[0];
    const float* net       = (const float*)d_in[1];
    const float* tau       = (const float*)d_in[2];
    const float* vec_g[4]  = {(const float*)d_in[3], (const float*)d_in[4],
                              (const float*)d_in[5], (const float*)d_in[6]};
    const float* tau_g[4]  = {(const float*)d_in[7], (const float*)d_in[8],
                              (const float*)d_in[9], (const float*)d_in[10]};
    const float* vec_pe_w  = (const float*)d_in[11];
    const float* tau_pe_w  = (const float*)d_in[12];
    const float* tau_pe_b  = (const float*)d_in[13];
    const float* vec_scale = (const float*)d_in[14];
    const float* vec_map_w = (const float*)d_in[15];
    const float* tau_mlp_w = (const float*)d_in[16];
    const float* vec_mlp_w = (const float*)d_in[17];
    const float* tau_params= (const float*)d_in[18];
    const float* last_w    = (const float*)d_in[19];
    float* out = (float*)d_out;

    transpose_level<<<16,   NTH>>>(vec_g[0], tau_g[0], 4096,   0LL);
    transpose_level<<<128,  NTH>>>(vec_g[1], tau_g[1], 32768,  4096LL * 32);
    transpose_level<<<1024, NTH>>>(vec_g[2], tau_g[2], 262144, 36864LL * 32);
    transpose_level<<<3456, NTH>>>(vec_g[3], tau_g[3], 884736, 299008LL * 32);

    cudaFuncSetAttribute(fused_kernel, cudaFuncAttributeMaxDynamicSharedMemorySize, 141824);
    fused_kernel<<<4096, NTH, 141824>>>(phys, net, tau,
                                        vec_pe_w, tau_pe_w, tau_pe_b, vec_scale,
                                        vec_map_w, tau_mlp_w, vec_mlp_w, tau_params,
                                        last_w, out);
}

// round 4
// speedup vs baseline: 1.4142x; 1.4142x over previous
#include <cuda_runtime.h>
#include <cuda_bf16.h>
#include <cstdint>

#define NTH 512
#define BP  128

// Combined channel-last bf16 grids: levels S=16,32,64,96, 32 channels each
// voxel offsets: 0, 4096, 36864, 299008 ; total 1183744 voxels
#define TOT_VOX 1183744
__device__ __nv_bfloat16 g_comb[(size_t)TOT_VOX * 32];

// ---------------------------------------------------------------------------
// Prolog: (C,S,S,S) fp32 vec+tau -> channel-last bf16 combined (all 4 levels)
// ---------------------------------------------------------------------------
__global__ void transpose_all(const float* __restrict__ v0, const float* __restrict__ t0,
                              const float* __restrict__ v1, const float* __restrict__ t1,
                              const float* __restrict__ v2, const float* __restrict__ t2,
                              const float* __restrict__ v3, const float* __restrict__ t3)
{
    __shared__ float tile[32][257];
    const int b = blockIdx.x;
    const float* vec; const float* tau; int vol; long long outBase; int vbase;
    if (b < 16)        { vec = v0; tau = t0; vol = 4096;   outBase = 0LL;          vbase = b * 256; }
    else if (b < 144)  { vec = v1; tau = t1; vol = 32768;  outBase = 4096LL * 32;  vbase = (b - 16) * 256; }
    else if (b < 1168) { vec = v2; tau = t2; vol = 262144; outBase = 36864LL * 32; vbase = (b - 144) * 256; }
    else               { vec = v3; tau = t3; vol = 884736; outBase = 299008LL * 32; vbase = (b - 1168) * 256; }

    const int tid = threadIdx.x;
    for (int i = tid; i < 32 * 256; i += 256) {
        int ch = i >> 8, vl = i & 255, v = vbase + vl;
        float val = 0.f;
        if (v < vol)
            val = (ch < 16) ? vec[(size_t)ch * vol + v]
                            : tau[(size_t)(ch - 16) * vol + v];
        tile[ch][vl] = val;
    }
    __syncthreads();
    __nv_bfloat16* out = g_comb + outBase;
    for (int i = tid; i < 16 * 256; i += 256) {
        int vl = i >> 4, cp = i & 15, v = vbase + vl;
        if (v < vol) {
            __nv_bfloat162 val = __floats2bfloat162_rn(tile[2 * cp][vl], tile[2 * cp + 1][vl]);
            *reinterpret_cast<__nv_bfloat162*>(out + (size_t)v * 32 + 2 * cp) = val;
        }
    }
}

// ---------------------------------------------------------------------------
// Math helpers
// ---------------------------------------------------------------------------
__device__ __forceinline__ float silu_f(float x) {
    return x * __fdividef(1.f, 1.f + __expf(-x));
}
__device__ __forceinline__ float tanh_f(float x) {
    float ax = fabsf(x);
    if (ax < 0.25f) {
        float x2 = x * x;
        return x * (1.f + x2 * (-0.333333333f + x2 * (0.133333333f - 0.0539682540f * x2)));
    }
    float e = __expf(2.f * x);
    return 1.f - __fdividef(2.f, e + 1.f);
}

__device__ __forceinline__ void accum8(float* acc, uint4 q, float w) {
    float2 f;
    f = __bfloat1622float2(*reinterpret_cast<__nv_bfloat162*>(&q.x));
    acc[0] = fmaf(w, f.x, acc[0]); acc[1] = fmaf(w, f.y, acc[1]);
    f = __bfloat1622float2(*reinterpret_cast<__nv_bfloat162*>(&q.y));
    acc[2] = fmaf(w, f.x, acc[2]); acc[3] = fmaf(w, f.y, acc[3]);
    f = __bfloat1622float2(*reinterpret_cast<__nv_bfloat162*>(&q.z));
    acc[4] = fmaf(w, f.x, acc[4]); acc[5] = fmaf(w, f.y, acc[5]);
    f = __bfloat1622float2(*reinterpret_cast<__nv_bfloat162*>(&q.w));
    acc[6] = fmaf(w, f.x, acc[6]); acc[7] = fmaf(w, f.y, acc[7]);
}

// Trilinear sample of one level (16 vec + 16 tau channels), silu applied
template<int S>
__device__ __forceinline__ void sample_level(int chBase, long long voxOff,
                                             float cx, float cy, float cz, int p,
                                             __nv_bfloat16* sA, __nv_bfloat16* sT)
{
    const float s1 = (float)(S - 1);
    float px = fminf(fmaxf((cx + 1.f) * 0.5f * s1, 0.f), s1);
    float py = fminf(fmaxf((cy + 1.f) * 0.5f * s1, 0.f), s1);
    float pz = fminf(fmaxf((cz + 1.f) * 0.5f * s1, 0.f), s1);
    int x0 = (int)px, y0 = (int)py, z0 = (int)pz;
    float wx = px - (float)x0, wy = py - (float)y0, wz = pz - (float)z0;
    int x1 = min(x0 + 1, S - 1), y1 = min(y0 + 1, S - 1), z1 = min(z0 + 1, S - 1);

    const __nv_bfloat16* g = g_comb + voxOff * 32;
    float acc[32];
#pragma unroll
    for (int i = 0; i < 32; i++) acc[i] = 0.f;

    const int   xs[2]  = {x0, x1}, ys[2] = {y0, y1}, zs[2] = {z0, z1};
    const float wxs[2] = {1.f - wx, wx}, wys[2] = {1.f - wy, wy}, wzs[2] = {1.f - wz, wz};
#pragma unroll
    for (int a = 0; a < 2; a++)
#pragma unroll
        for (int b = 0; b < 2; b++)
#pragma unroll
            for (int c = 0; c < 2; c++) {
                float w = wzs[a] * wys[b] * wxs[c];
                const uint4* q = reinterpret_cast<const uint4*>(
                    g + (size_t)((zs[a] * S + ys[b]) * S + xs[c]) * 32);
                uint4 q0 = q[0], q1 = q[1], q2 = q[2], q3 = q[3];
                accum8(acc + 0,  q0, w);
                accum8(acc + 8,  q1, w);
                accum8(acc + 16, q2, w);
                accum8(acc + 24, q3, w);
            }
#pragma unroll
    for (int c = 0; c < 16; c += 2) {
        *reinterpret_cast<__nv_bfloat162*>(&sA[p * 136 + chBase + c]) =
            __floats2bfloat162_rn(silu_f(acc[c]), silu_f(acc[c + 1]));
        *reinterpret_cast<__nv_bfloat162*>(&sT[p * 136 + chBase + c]) =
            __floats2bfloat162_rn(silu_f(acc[16 + c]), silu_f(acc[16 + c + 1]));
    }
}

// Cooperative fp32 -> bf16 weight load into smem (row stride 136 bf16)
__device__ __forceinline__ void load_w(const float* __restrict__ W, __nv_bfloat16* sW)
{
    const int tid = threadIdx.x;
#pragma unroll 2
    for (int i = tid; i < 128 * 32; i += NTH) {
        int r = i >> 5, c4 = (i & 31) * 4;
        float4 f = *reinterpret_cast<const float4*>(W + r * 128 + c4);
        *reinterpret_cast<__nv_bfloat162*>(sW + r * 136 + c4)     = __floats2bfloat162_rn(f.x, f.y);
        *reinterpret_cast<__nv_bfloat162*>(sW + r * 136 + c4 + 2) = __floats2bfloat162_rn(f.z, f.w);
    }
}

// ---------------------------------------------------------------------------
// mma.sync helpers
// ---------------------------------------------------------------------------
__device__ __forceinline__ void ldm4(uint32_t& r0, uint32_t& r1, uint32_t& r2, uint32_t& r3,
                                     uint32_t addr)
{
    asm volatile("ldmatrix.sync.aligned.m8n8.x4.shared.b16 {%0,%1,%2,%3}, [%4];\n"
                 : "=r"(r0), "=r"(r1), "=r"(r2), "=r"(r3) : "r"(addr));
}
__device__ __forceinline__ void mma16816(float* c, const uint32_t* a, const uint32_t* b)
{
    asm volatile(
        "mma.sync.aligned.m16n8k16.row.col.f32.bf16.bf16.f32 "
        "{%0,%1,%2,%3},{%4,%5,%6,%7},{%8,%9},{%0,%1,%2,%3};\n"
        : "+f"(c[0]), "+f"(c[1]), "+f"(c[2]), "+f"(c[3])
        : "r"(a[0]), "r"(a[1]), "r"(a[2]), "r"(a[3]), "r"(b[0]), "r"(b[1]));
}

// C[p][j] = sum_k A[p][k] * W[j][k], 128x128x128, bf16 in / fp32 acc.
// 16 warps: warp tile 32(m) x 32(n); frag grid 2 x 4 of m16n8k16.
__device__ __forceinline__ void gemm128(const __nv_bfloat16* A, const __nv_bfloat16* W,
                                        float (&acc)[2][4][4], int lane, int m0, int n0)
{
#pragma unroll
    for (int mi = 0; mi < 2; mi++)
#pragma unroll
        for (int ni = 0; ni < 4; ni++)
#pragma unroll
            for (int t = 0; t < 4; t++) acc[mi][ni][t] = 0.f;

    uint32_t aBase = (uint32_t)__cvta_generic_to_shared(A)
                   + (uint32_t)((m0 + (lane & 15)) * 272 + (lane >> 4) * 16);
    uint32_t bBase = (uint32_t)__cvta_generic_to_shared(W)
                   + (uint32_t)((n0 + (lane & 7) + ((lane >> 4) << 3)) * 272
                                + ((lane >> 3) & 1) * 16);
#pragma unroll
    for (int k = 0; k < 8; k++) {
        uint32_t a[2][4];
        ldm4(a[0][0], a[0][1], a[0][2], a[0][3], aBase + k * 32);
        ldm4(a[1][0], a[1][1], a[1][2], a[1][3], aBase + 16 * 272 + k * 32);
        uint32_t b[4][2];
#pragma unroll
        for (int t = 0; t < 2; t++) {
            uint32_t r0, r1, r2, r3;
            ldm4(r0, r1, r2, r3, bBase + t * (16 * 272) + k * 32);
            b[2 * t][0] = r0; b[2 * t][1] = r1;
            b[2 * t + 1][0] = r2; b[2 * t + 1][1] = r3;
        }
#pragma unroll
        for (int mi = 0; mi < 2; mi++)
#pragma unroll
            for (int ni = 0; ni < 4; ni++)
                mma16816(acc[mi][ni], a[mi], b[ni]);
    }
}

// ---------------------------------------------------------------------------
// Fused main kernel: 128 points per block, 512 threads
// ---------------------------------------------------------------------------
__global__ void __launch_bounds__(NTH, 1)
fused_kernel(const float* __restrict__ phys, const float* __restrict__ net,
             const float* __restrict__ tauIn,
             const float* __restrict__ vec_pe_w, const float* __restrict__ tau_pe_w,
             const float* __restrict__ tau_pe_b, const float* __restrict__ vec_scale,
             const float* __restrict__ vec_map_w, const float* __restrict__ tau_mlp_w,
             const float* __restrict__ vec_mlp_w, const float* __restrict__ tau_params,
             const float* __restrict__ last_w, float* __restrict__ outG)
{
    extern __shared__ char smem[];
    __nv_bfloat16* sA0 = (__nv_bfloat16*)(smem);            // 34816 B
    __nv_bfloat16* sA1 = (__nv_bfloat16*)(smem + 34816);    // 34816 B
    __nv_bfloat16* sT  = (__nv_bfloat16*)(smem + 69632);    // 34816 B
    __nv_bfloat16* sW  = (__nv_bfloat16*)(smem + 104448);   // 34816 B
    float* sTau   = (float*)(smem + 139264);                // 512 B
    float* sScale = (float*)(smem + 139776);                // 512 B
    float* sCx    = (float*)(smem + 140288);
    float* sCy    = (float*)(smem + 140800);
    float* sCz    = (float*)(smem + 141312);                // end 141824
    float* sOutF  = (float*)(smem);                         // 128*132*4 (reuse)

    const int tid = threadIdx.x;
    const int p0  = blockIdx.x * BP;

    if (tid < BP) {
        int gp = p0 + tid;
        sCx[tid]  = net[gp * 3 + 0];
        sCy[tid]  = net[gp * 3 + 1];
        sCz[tid]  = net[gp * 3 + 2];
        sTau[tid] = tauIn[gp];
        sScale[tid] = vec_scale[tid];
    }
    __syncthreads();

    // ---- sampling + FFM: 4 warp-groups, one level each + 1/4 of FFM ----
    {
        int p = tid & 127, task = tid >> 7;
        float cx = sCx[p], cy = sCy[p], cz = sCz[p];
        if (task == 0)      sample_level<16>(0,  0LL,      cx, cy, cz, p, sA0, sT);
        else if (task == 1) sample_level<32>(16, 4096LL,   cx, cy, cz, p, sA0, sT);
        else if (task == 2) sample_level<64>(32, 36864LL,  cx, cy, cz, p, sA0, sT);
        else                sample_level<96>(48, 299008LL, cx, cy, cz, p, sA0, sT);

        if (task < 2) {
            const float* w = vec_pe_w;
            int jlo = task * 32;
#pragma unroll 4
            for (int j = jlo; j < jlo + 32; j++) {
                float d = cx * w[j * 3] + cy * w[j * 3 + 1] + cz * w[j * 3 + 2];
                sA0[p * 136 + 64 + j] = __float2bfloat16(__sinf(d));
            }
        } else {
            const float* w = tau_pe_w;
            int jlo = (task - 2) * 32;
#pragma unroll 4
            for (int j = jlo; j < jlo + 32; j++) {
                float d = cx * w[j * 3] + cy * w[j * 3 + 1] + cz * w[j * 3 + 2] + tau_pe_b[j];
                sT[p * 136 + 64 + j] = __float2bfloat16(__sinf(d));
            }
        }
    }
    __syncthreads();

    const int lane = tid & 31, wid = tid >> 5;
    const int m0 = (wid & 3) * 32, n0 = (wid >> 2) * 32;
    float acc[2][4][4];
    float outF[2][4][4];

    // ---- vec_map layer 0 ----
    load_w(vec_map_w, sW);
    __syncthreads();
    gemm128(sA0, sW, acc, lane, m0, n0);
#pragma unroll
    for (int mi = 0; mi < 2; mi++)
#pragma unroll
        for (int ni = 0; ni < 4; ni++)
#pragma unroll
            for (int hi = 0; hi < 2; hi++) {
                int p = m0 + mi * 16 + (lane >> 2) + hi * 8;
                int j = n0 + ni * 8 + (lane & 3) * 2;
                *reinterpret_cast<__nv_bfloat162*>(&sA1[p * 136 + j]) =
                    __floats2bfloat162_rn(silu_f(acc[mi][ni][hi * 2]),
                                          silu_f(acc[mi][ni][hi * 2 + 1]));
            }
    __syncthreads();

    // ---- vec_map layer 1 + out init: out = tanh(tau*scale*silu(h)) ----
    load_w(vec_map_w + 128 * 128, sW);
    __syncthreads();
    gemm128(sA1, sW, acc, lane, m0, n0);
#pragma unroll
    for (int mi = 0; mi < 2; mi++)
#pragma unroll
        for (int ni = 0; ni < 4; ni++)
#pragma unroll
            for (int hi = 0; hi < 2; hi++) {
                int p = m0 + mi * 16 + (lane >> 2) + hi * 8;
                int j = n0 + ni * 8 + (lane & 3) * 2;
                float tp = sTau[p];
                float s0 = sScale[j], s1 = sScale[j + 1];
                float o0 = tanh_f(tp * s0 * silu_f(acc[mi][ni][hi * 2]));
                float o1 = tanh_f(tp * s1 * silu_f(acc[mi][ni][hi * 2 + 1]));
                outF[mi][ni][hi * 2]     = o0;
                outF[mi][ni][hi * 2 + 1] = o1;
                *reinterpret_cast<__nv_bfloat162*>(&sA0[p * 136 + j]) =
                    __floats2bfloat162_rn(o0, o1);
            }
    __syncthreads();

    // ---- tau path: ttt = tauF @ tau_mlp_w^T (stored bf16 into sT) ----
    load_w(tau_mlp_w, sW);
    __syncthreads();
    gemm128(sT, sW, acc, lane, m0, n0);
    __syncthreads();
#pragma unroll
    for (int mi = 0; mi < 2; mi++)
#pragma unroll
        for (int ni = 0; ni < 4; ni++)
#pragma unroll
            for (int hi = 0; hi < 2; hi++) {
                int p = m0 + mi * 16 + (lane >> 2) + hi * 8;
                int j = n0 + ni * 8 + (lane & 3) * 2;
                *reinterpret_cast<__nv_bfloat162*>(&sT[p * 136 + j]) =
                    __floats2bfloat162_rn(acc[mi][ni][hi * 2], acc[mi][ni][hi * 2 + 1]);
            }
    __syncthreads();

    // ---- 3 residual layers ----
#pragma unroll 1
    for (int idx = 0; idx < 3; idx++) {
        load_w(vec_mlp_w + idx * 128 * 128, sW);
        __syncthreads();
        const __nv_bfloat16* Abuf = (idx & 1) ? sA1 : sA0;
        __nv_bfloat16*       Bout = (idx & 1) ? sA0 : sA1;
        gemm128(Abuf, sW, acc, lane, m0, n0);
        const float* tpar = tau_params + idx * 128;
#pragma unroll
        for (int mi = 0; mi < 2; mi++)
#pragma unroll
            for (int ni = 0; ni < 4; ni++)
#pragma unroll
                for (int hi = 0; hi < 2; hi++) {
                    int p = m0 + mi * 16 + (lane >> 2) + hi * 8;
                    int j = n0 + ni * 8 + (lane & 3) * 2;
                    float h0 = acc[mi][ni][hi * 2], h1 = acc[mi][ni][hi * 2 + 1];
                    if (idx == 0) {
                        float2 t = __bfloat1622float2(
                            *reinterpret_cast<__nv_bfloat162*>(&sT[p * 136 + j]));
                        h0 *= t.x; h1 *= t.y;
                    }
                    float tp = sTau[p];
                    float tt0 = tanh_f(tp * __ldg(&tpar[j]));
                    float tt1 = tanh_f(tp * __ldg(&tpar[j + 1]));
                    float o0 = outF[mi][ni][hi * 2]     + tt0 * silu_f(h0);
                    float o1 = outF[mi][ni][hi * 2 + 1] + tt1 * silu_f(h1);
                    outF[mi][ni][hi * 2]     = o0;
                    outF[mi][ni][hi * 2 + 1] = o1;
                    if (idx < 2)
                        *reinterpret_cast<__nv_bfloat162*>(&Bout[p * 136 + j]) =
                            __floats2bfloat162_rn(o0, o1);
                }
        __syncthreads();
    }

    // ---- spill fp32 out to smem (reuses sA0/sA1 region) ----
#pragma unroll
    for (int mi = 0; mi < 2; mi++)
#pragma unroll
        for (int ni = 0; ni < 4; ni++)
#pragma unroll
            for (int hi = 0; hi < 2; hi++) {
                int p = m0 + mi * 16 + (lane >> 2) + hi * 8;
                int j = n0 + ni * 8 + (lane & 3) * 2;
                *reinterpret_cast<float2*>(&sOutF[p * 132 + j]) =
                    make_float2(outF[mi][ni][hi * 2], outF[mi][ni][hi * 2 + 1]);
            }
    __syncthreads();

    // ---- head: res = phys + out @ last_w^T ----
    if (tid < BP) {
        int p = tid;
        float a0 = 0.f, a1 = 0.f, a2 = 0.f;
#pragma unroll 8
        for (int j = 0; j < 128; j += 4) {
            float4 o  = *reinterpret_cast<float4*>(&sOutF[p * 132 + j]);
            float4 w0 = __ldg(reinterpret_cast<const float4*>(last_w + j));
            float4 w1 = __ldg(reinterpret_cast<const float4*>(last_w + 128 + j));
            float4 w2 = __ldg(reinterpret_cast<const float4*>(last_w + 256 + j));
            a0 += o.x * w0.x + o.y * w0.y + o.z * w0.z + o.w * w0.w;
            a1 += o.x * w1.x + o.y * w1.y + o.z * w1.z + o.w * w1.w;
            a2 += o.x * w2.x + o.y * w2.y + o.z * w2.z + o.w * w2.w;
        }
        long long gp = (long long)(p0 + p) * 3;
        outG[gp + 0] = phys[gp + 0] + a0;
        outG[gp + 1] = phys[gp + 1] + a1;
        outG[gp + 2] = phys[gp + 2] + a2;
    }
}

// ---------------------------------------------------------------------------
extern "C" void kernel_launch(void* const* d_in, const int* in_sizes, int n_in,
                              void* d_out, int out_size)
{
    const float* phys      = (const float*)d_in[0];
    const float* net       = (const float*)d_in[1];
    const float* tau       = (const float*)d_in[2];
    const float* vec_g[4]  = {(const float*)d_in[3], (const float*)d_in[4],
                              (const float*)d_in[5], (const float*)d_in[6]};
    const float* tau_g[4]  = {(const float*)d_in[7], (const float*)d_in[8],
                              (const float*)d_in[9], (const float*)d_in[10]};
    const float* vec_pe_w  = (const float*)d_in[11];
    const float* tau_pe_w  = (const float*)d_in[12];
    const float* tau_pe_b  = (const float*)d_in[13];
    const float* vec_scale = (const float*)d_in[14];
    const float* vec_map_w = (const float*)d_in[15];
    const float* tau_mlp_w = (const float*)d_in[16];
    const float* vec_mlp_w = (const float*)d_in[17];
    const float* tau_params= (const float*)d_in[18];
    const float* last_w    = (const float*)d_in[19];
    float* out = (float*)d_out;

    transpose_all<<<4624, 256>>>(vec_g[0], tau_g[0], vec_g[1], tau_g[1],
                                 vec_g[2], tau_g[2], vec_g[3], tau_g[3]);

    cudaFuncSetAttribute(fused_kernel, cudaFuncAttributeMaxDynamicSharedMemorySize, 141824);
    fused_kernel<<<4096, NTH, 141824>>>(phys, net, tau,
                                        vec_pe_w, tau_pe_w, tau_pe_b, vec_scale,
                                        vec_map_w, tau_mlp_w, vec_mlp_w, tau_params,
                                        last_w, out);
}

// round 5
// speedup vs baseline: 1.5326x; 1.0837x over previous
#include <cuda_runtime.h>
#include <cuda_bf16.h>
#include <cstdint>

#define NTH 256
#define BP  64

// Combined channel-last bf16 grids: levels S=16,32,64,96, 32 channels each
// voxel offsets: 0, 4096, 36864, 299008 ; total 1183744 voxels
#define TOT_VOX 1183744
__device__ __align__(16) __nv_bfloat16 g_comb[(size_t)TOT_VOX * 32];
// 6 weight matrices pre-converted to bf16, row stride 136 (smem-ready layout)
// order: vec_map0, vec_map1, tau_mlp, vec_mlp0, vec_mlp1, vec_mlp2
__device__ __align__(16) __nv_bfloat16 g_wbf[6 * 128 * 136];

// ---------------------------------------------------------------------------
// Prolog A: (C,S,S,S) fp32 vec+tau -> channel-last bf16 combined (all levels)
// ---------------------------------------------------------------------------
__global__ void transpose_all(const float* __restrict__ v0, const float* __restrict__ t0,
                              const float* __restrict__ v1, const float* __restrict__ t1,
                              const float* __restrict__ v2, const float* __restrict__ t2,
                              const float* __restrict__ v3, const float* __restrict__ t3)
{
    __shared__ float tile[32][257];
    const int b = blockIdx.x;
    const float* vec; const float* tau; int vol; long long outBase; int vbase;
    if (b < 16)        { vec = v0; tau = t0; vol = 4096;   outBase = 0LL;           vbase = b * 256; }
    else if (b < 144)  { vec = v1; tau = t1; vol = 32768;  outBase = 4096LL * 32;   vbase = (b - 16) * 256; }
    else if (b < 1168) { vec = v2; tau = t2; vol = 262144; outBase = 36864LL * 32;  vbase = (b - 144) * 256; }
    else               { vec = v3; tau = t3; vol = 884736; outBase = 299008LL * 32; vbase = (b - 1168) * 256; }

    const int tid = threadIdx.x;
    for (int i = tid; i < 32 * 256; i += 256) {
        int ch = i >> 8, vl = i & 255, v = vbase + vl;
        float val = 0.f;
        if (v < vol)
            val = (ch < 16) ? vec[(size_t)ch * vol + v]
                            : tau[(size_t)(ch - 16) * vol + v];
        tile[ch][vl] = val;
    }
    __syncthreads();
    __nv_bfloat16* out = g_comb + outBase;
    for (int i = tid; i < 16 * 256; i += 256) {
        int vl = i >> 4, cp = i & 15, v = vbase + vl;
        if (v < vol) {
            __nv_bfloat162 val = __floats2bfloat162_rn(tile[2 * cp][vl], tile[2 * cp + 1][vl]);
            *reinterpret_cast<__nv_bfloat162*>(out + (size_t)v * 32 + 2 * cp) = val;
        }
    }
}

// ---------------------------------------------------------------------------
// Prolog B: convert 6 weight matrices fp32 -> bf16 stride-136
// ---------------------------------------------------------------------------
__global__ void conv_weights(const float* __restrict__ vec_map_w,
                             const float* __restrict__ tau_mlp_w,
                             const float* __restrict__ vec_mlp_w)
{
    int i = blockIdx.x * 256 + threadIdx.x;          // 0 .. 6*128*32-1
    if (i >= 6 * 128 * 32) return;
    int mat = i >> 12;                               // /4096
    int r   = (i >> 5) & 127;
    int c4  = (i & 31) * 4;
    const float* src = (mat == 0) ? vec_map_w
                     : (mat == 1) ? vec_map_w + 16384
                     : (mat == 2) ? tau_mlp_w
                                  : vec_mlp_w + (mat - 3) * 16384;
    float4 f = *reinterpret_cast<const float4*>(src + r * 128 + c4);
    __nv_bfloat16* dst = g_wbf + (size_t)mat * 128 * 136 + r * 136 + c4;
    *reinterpret_cast<__nv_bfloat162*>(dst)     = __floats2bfloat162_rn(f.x, f.y);
    *reinterpret_cast<__nv_bfloat162*>(dst + 2) = __floats2bfloat162_rn(f.z, f.w);
}

// ---------------------------------------------------------------------------
// Math helpers
// ---------------------------------------------------------------------------
__device__ __forceinline__ float silu_f(float x) {
    return x * __fdividef(1.f, 1.f + __expf(-x));
}
__device__ __forceinline__ float tanh_f(float x) {
    float ax = fabsf(x);
    if (ax < 0.25f) {
        float x2 = x * x;
        return x * (1.f + x2 * (-0.333333333f + x2 * (0.133333333f - 0.0539682540f * x2)));
    }
    float e = __expf(2.f * x);
    return 1.f - __fdividef(2.f, e + 1.f);
}

__device__ __forceinline__ void accum8(float* acc, uint4 q, float w) {
    float2 f;
    f = __bfloat1622float2(*reinterpret_cast<__nv_bfloat162*>(&q.x));
    acc[0] = fmaf(w, f.x, acc[0]); acc[1] = fmaf(w, f.y, acc[1]);
    f = __bfloat1622float2(*reinterpret_cast<__nv_bfloat162*>(&q.y));
    acc[2] = fmaf(w, f.x, acc[2]); acc[3] = fmaf(w, f.y, acc[3]);
    f = __bfloat1622float2(*reinterpret_cast<__nv_bfloat162*>(&q.z));
    acc[4] = fmaf(w, f.x, acc[4]); acc[5] = fmaf(w, f.y, acc[5]);
    f = __bfloat1622float2(*reinterpret_cast<__nv_bfloat162*>(&q.w));
    acc[6] = fmaf(w, f.x, acc[6]); acc[7] = fmaf(w, f.y, acc[7]);
}

// Trilinear sample of one level (16 vec + 16 tau channels), silu applied
template<int S>
__device__ __forceinline__ void sample_level(int chBase, long long voxOff,
                                             float cx, float cy, float cz, int p,
                                             __nv_bfloat16* sA, __nv_bfloat16* sT)
{
    const float s1 = (float)(S - 1);
    float px = fminf(fmaxf((cx + 1.f) * 0.5f * s1, 0.f), s1);
    float py = fminf(fmaxf((cy + 1.f) * 0.5f * s1, 0.f), s1);
    float pz = fminf(fmaxf((cz + 1.f) * 0.5f * s1, 0.f), s1);
    int x0 = (int)px, y0 = (int)py, z0 = (int)pz;
    float wx = px - (float)x0, wy = py - (float)y0, wz = pz - (float)z0;
    int x1 = min(x0 + 1, S - 1), y1 = min(y0 + 1, S - 1), z1 = min(z0 + 1, S - 1);

    const __nv_bfloat16* g = g_comb + voxOff * 32;
    float acc[32];
#pragma unroll
    for (int i = 0; i < 32; i++) acc[i] = 0.f;

    const int   xs[2]  = {x0, x1}, ys[2] = {y0, y1}, zs[2] = {z0, z1};
    const float wxs[2] = {1.f - wx, wx}, wys[2] = {1.f - wy, wy}, wzs[2] = {1.f - wz, wz};
#pragma unroll
    for (int a = 0; a < 2; a++)
#pragma unroll
        for (int b = 0; b < 2; b++)
#pragma unroll
            for (int c = 0; c < 2; c++) {
                float w = wzs[a] * wys[b] * wxs[c];
                const uint4* q = reinterpret_cast<const uint4*>(
                    g + (size_t)((zs[a] * S + ys[b]) * S + xs[c]) * 32);
                uint4 q0 = q[0], q1 = q[1], q2 = q[2], q3 = q[3];
                accum8(acc + 0,  q0, w);
                accum8(acc + 8,  q1, w);
                accum8(acc + 16, q2, w);
                accum8(acc + 24, q3, w);
            }
#pragma unroll
    for (int c = 0; c < 16; c += 2) {
        *reinterpret_cast<__nv_bfloat162*>(&sA[p * 136 + chBase + c]) =
            __floats2bfloat162_rn(silu_f(acc[c]), silu_f(acc[c + 1]));
        *reinterpret_cast<__nv_bfloat162*>(&sT[p * 136 + chBase + c]) =
            __floats2bfloat162_rn(silu_f(acc[16 + c]), silu_f(acc[16 + c + 1]));
    }
}

// Cooperative bf16 weight copy (global, already stride-136) -> smem
__device__ __forceinline__ void load_w(int mat, __nv_bfloat16* sW)
{
    const uint4* src = reinterpret_cast<const uint4*>(g_wbf + (size_t)mat * 128 * 136);
    uint4* dst = reinterpret_cast<uint4*>(sW);
    const int tid = threadIdx.x;
#pragma unroll
    for (int i = 0; i < 8; i++)
        dst[tid + i * NTH] = src[tid + i * NTH];
    int i8 = tid + 8 * NTH;
    if (i8 < 2176) dst[i8] = src[i8];
}

// ---------------------------------------------------------------------------
// mma.sync helpers
// ---------------------------------------------------------------------------
__device__ __forceinline__ void ldm4(uint32_t& r0, uint32_t& r1, uint32_t& r2, uint32_t& r3,
                                     uint32_t addr)
{
    asm volatile("ldmatrix.sync.aligned.m8n8.x4.shared.b16 {%0,%1,%2,%3}, [%4];\n"
                 : "=r"(r0), "=r"(r1), "=r"(r2), "=r"(r3) : "r"(addr));
}
__device__ __forceinline__ void mma16816(float* c, const uint32_t* a, const uint32_t* b)
{
    asm volatile(
        "mma.sync.aligned.m16n8k16.row.col.f32.bf16.bf16.f32 "
        "{%0,%1,%2,%3},{%4,%5,%6,%7},{%8,%9},{%0,%1,%2,%3};\n"
        : "+f"(c[0]), "+f"(c[1]), "+f"(c[2]), "+f"(c[3])
        : "r"(a[0]), "r"(a[1]), "r"(a[2]), "r"(a[3]), "r"(b[0]), "r"(b[1]));
}

// C[p][j] = sum_k A[p][k] * W[j][k], 64x128x128, bf16 in / fp32 acc.
// 8 warps: warp tile 32(m) x 32(n); frag grid 2 x 4 of m16n8k16.
__device__ __forceinline__ void gemm64(const __nv_bfloat16* A, const __nv_bfloat16* W,
                                       float (&acc)[2][4][4], int lane, int m0, int n0)
{
#pragma unroll
    for (int mi = 0; mi < 2; mi++)
#pragma unroll
        for (int ni = 0; ni < 4; ni++)
#pragma unroll
            for (int t = 0; t < 4; t++) acc[mi][ni][t] = 0.f;

    uint32_t aBase = (uint32_t)__cvta_generic_to_shared(A)
                   + (uint32_t)((m0 + (lane & 15)) * 272 + (lane >> 4) * 16);
    uint32_t bBase = (uint32_t)__cvta_generic_to_shared(W)
                   + (uint32_t)((n0 + (lane & 7) + ((lane >> 4) << 3)) * 272
                                + ((lane >> 3) & 1) * 16);
#pragma unroll
    for (int k = 0; k < 8; k++) {
        uint32_t a[2][4];
        ldm4(a[0][0], a[0][1], a[0][2], a[0][3], aBase + k * 32);
        ldm4(a[1][0], a[1][1], a[1][2], a[1][3], aBase + 16 * 272 + k * 32);
        uint32_t b[4][2];
#pragma unroll
        for (int t = 0; t < 2; t++) {
            uint32_t r0, r1, r2, r3;
            ldm4(r0, r1, r2, r3, bBase + t * (16 * 272) + k * 32);
            b[2 * t][0] = r0; b[2 * t][1] = r1;
            b[2 * t + 1][0] = r2; b[2 * t + 1][1] = r3;
        }
#pragma unroll
        for (int mi = 0; mi < 2; mi++)
#pragma unroll
            for (int ni = 0; ni < 4; ni++)
                mma16816(acc[mi][ni], a[mi], b[ni]);
    }
}

// ---------------------------------------------------------------------------
// Fused main kernel: 64 points per block, 256 threads, 2 CTAs/SM
// ---------------------------------------------------------------------------
__global__ void __launch_bounds__(NTH, 2)
fused_kernel(const float* __restrict__ phys, const float* __restrict__ net,
             const float* __restrict__ tauIn,
             const float* __restrict__ vec_pe_w, const float* __restrict__ tau_pe_w,
             const float* __restrict__ tau_pe_b, const float* __restrict__ vec_scale,
             const float* __restrict__ tau_params,
             const float* __restrict__ last_w, float* __restrict__ outG)
{
    extern __shared__ char smem[];
    __nv_bfloat16* sA0 = (__nv_bfloat16*)(smem);            // 17408 B
    __nv_bfloat16* sA1 = (__nv_bfloat16*)(smem + 17408);    // 17408 B
    __nv_bfloat16* sT  = (__nv_bfloat16*)(smem + 34816);    // 17408 B
    __nv_bfloat16* sW  = (__nv_bfloat16*)(smem + 52224);    // 34816 B
    float* sTau   = (float*)(smem + 87040);                 // 256 B
    float* sScale = (float*)(smem + 87296);                 // 512 B
    float* sCx    = (float*)(smem + 87808);                 // 256 B
    float* sCy    = (float*)(smem + 88064);                 // 256 B
    float* sCz    = (float*)(smem + 88320);                 // end 88576
    float* sOutF  = (float*)(smem);                         // 64*132*4 = 33792 (reuse)

    const int tid = threadIdx.x;
    const int p0  = blockIdx.x * BP;

    if (tid < BP) {
        int gp = p0 + tid;
        sCx[tid]  = net[gp * 3 + 0];
        sCy[tid]  = net[gp * 3 + 1];
        sCz[tid]  = net[gp * 3 + 2];
        sTau[tid] = tauIn[gp];
    }
    if (tid < 128) sScale[tid] = vec_scale[tid];
    __syncthreads();

    // ---- sampling + FFM: 4 groups of 64 threads, one level each ----
    {
        int p = tid & 63, task = tid >> 6;
        float cx = sCx[p], cy = sCy[p], cz = sCz[p];
        if (task == 0)      sample_level<16>(0,  0LL,      cx, cy, cz, p, sA0, sT);
        else if (task == 1) sample_level<32>(16, 4096LL,   cx, cy, cz, p, sA0, sT);
        else if (task == 2) sample_level<64>(32, 36864LL,  cx, cy, cz, p, sA0, sT);
        else                sample_level<96>(48, 299008LL, cx, cy, cz, p, sA0, sT);

        if (task < 2) {
            const float* w = vec_pe_w;
            int jlo = task * 32;
#pragma unroll 4
            for (int j = jlo; j < jlo + 32; j++) {
                float d = cx * w[j * 3] + cy * w[j * 3 + 1] + cz * w[j * 3 + 2];
                sA0[p * 136 + 64 + j] = __float2bfloat16(__sinf(d));
            }
        } else {
            const float* w = tau_pe_w;
            int jlo = (task - 2) * 32;
#pragma unroll 4
            for (int j = jlo; j < jlo + 32; j++) {
                float d = cx * w[j * 3] + cy * w[j * 3 + 1] + cz * w[j * 3 + 2] + tau_pe_b[j];
                sT[p * 136 + 64 + j] = __float2bfloat16(__sinf(d));
            }
        }
    }
    __syncthreads();

    const int lane = tid & 31, wid = tid >> 5;
    const int m0 = (wid & 1) * 32, n0 = (wid >> 1) * 32;
    float acc[2][4][4];
    float outF[2][4][4];

    // ---- vec_map layer 0 ----
    load_w(0, sW);
    __syncthreads();
    gemm64(sA0, sW, acc, lane, m0, n0);
#pragma unroll
    for (int mi = 0; mi < 2; mi++)
#pragma unroll
        for (int ni = 0; ni < 4; ni++)
#pragma unroll
            for (int hi = 0; hi < 2; hi++) {
                int p = m0 + mi * 16 + (lane >> 2) + hi * 8;
                int j = n0 + ni * 8 + (lane & 3) * 2;
                *reinterpret_cast<__nv_bfloat162*>(&sA1[p * 136 + j]) =
                    __floats2bfloat162_rn(silu_f(acc[mi][ni][hi * 2]),
                                          silu_f(acc[mi][ni][hi * 2 + 1]));
            }
    __syncthreads();

    // ---- vec_map layer 1 + out init: out = tanh(tau*scale*silu(h)) ----
    load_w(1, sW);
    __syncthreads();
    gemm64(sA1, sW, acc, lane, m0, n0);
#pragma unroll
    for (int mi = 0; mi < 2; mi++)
#pragma unroll
        for (int ni = 0; ni < 4; ni++)
#pragma unroll
            for (int hi = 0; hi < 2; hi++) {
                int p = m0 + mi * 16 + (lane >> 2) + hi * 8;
                int j = n0 + ni * 8 + (lane & 3) * 2;
                float tp = sTau[p];
                float s0 = sScale[j], s1 = sScale[j + 1];
                float o0 = tanh_f(tp * s0 * silu_f(acc[mi][ni][hi * 2]));
                float o1 = tanh_f(tp * s1 * silu_f(acc[mi][ni][hi * 2 + 1]));
                outF[mi][ni][hi * 2]     = o0;
                outF[mi][ni][hi * 2 + 1] = o1;
                *reinterpret_cast<__nv_bfloat162*>(&sA0[p * 136 + j]) =
                    __floats2bfloat162_rn(o0, o1);
            }
    __syncthreads();

    // ---- tau path: ttt = tauF @ tau_mlp_w^T (bf16 back into sT) ----
    load_w(2, sW);
    __syncthreads();
    gemm64(sT, sW, acc, lane, m0, n0);
    __syncthreads();
#pragma unroll
    for (int mi = 0; mi < 2; mi++)
#pragma unroll
        for (int ni = 0; ni < 4; ni++)
#pragma unroll
            for (int hi = 0; hi < 2; hi++) {
                int p = m0 + mi * 16 + (lane >> 2) + hi * 8;
                int j = n0 + ni * 8 + (lane & 3) * 2;
                *reinterpret_cast<__nv_bfloat162*>(&sT[p * 136 + j]) =
                    __floats2bfloat162_rn(acc[mi][ni][hi * 2], acc[mi][ni][hi * 2 + 1]);
            }
    __syncthreads();

    // ---- 3 residual layers ----
#pragma unroll 1
    for (int idx = 0; idx < 3; idx++) {
        load_w(3 + idx, sW);
        __syncthreads();
        const __nv_bfloat16* Abuf = (idx & 1) ? sA1 : sA0;
        __nv_bfloat16*       Bout = (idx & 1) ? sA0 : sA1;
        gemm64(Abuf, sW, acc, lane, m0, n0);
        const float* tpar = tau_params + idx * 128;
#pragma unroll
        for (int mi = 0; mi < 2; mi++)
#pragma unroll
            for (int ni = 0; ni < 4; ni++)
#pragma unroll
                for (int hi = 0; hi < 2; hi++) {
                    int p = m0 + mi * 16 + (lane >> 2) + hi * 8;
                    int j = n0 + ni * 8 + (lane & 3) * 2;
                    float h0 = acc[mi][ni][hi * 2], h1 = acc[mi][ni][hi * 2 + 1];
                    if (idx == 0) {
                        float2 t = __bfloat1622float2(
                            *reinterpret_cast<__nv_bfloat162*>(&sT[p * 136 + j]));
                        h0 *= t.x; h1 *= t.y;
                    }
                    float tp = sTau[p];
                    float tt0 = tanh_f(tp * __ldg(&tpar[j]));
                    float tt1 = tanh_f(tp * __ldg(&tpar[j + 1]));
                    float o0 = outF[mi][ni][hi * 2]     + tt0 * silu_f(h0);
                    float o1 = outF[mi][ni][hi * 2 + 1] + tt1 * silu_f(h1);
                    outF[mi][ni][hi * 2]     = o0;
                    outF[mi][ni][hi * 2 + 1] = o1;
                    if (idx < 2)
                        *reinterpret_cast<__nv_bfloat162*>(&Bout[p * 136 + j]) =
                            __floats2bfloat162_rn(o0, o1);
                }
        __syncthreads();
    }

    // ---- spill fp32 out to smem (reuses sA0/sA1 region) ----
#pragma unroll
    for (int mi = 0; mi < 2; mi++)
#pragma unroll
        for (int ni = 0; ni < 4; ni++)
#pragma unroll
            for (int hi = 0; hi < 2; hi++) {
                int p = m0 + mi * 16 + (lane >> 2) + hi * 8;
                int j = n0 + ni * 8 + (lane & 3) * 2;
                *reinterpret_cast<float2*>(&sOutF[p * 132 + j]) =
                    make_float2(outF[mi][ni][hi * 2], outF[mi][ni][hi * 2 + 1]);
            }
    __syncthreads();

    // ---- head: res = phys + out @ last_w^T ----
    if (tid < BP) {
        int p = tid;
        float a0 = 0.f, a1 = 0.f, a2 = 0.f;
#pragma unroll 8
        for (int j = 0; j < 128; j += 4) {
            float4 o  = *reinterpret_cast<float4*>(&sOutF[p * 132 + j]);
            float4 w0 = __ldg(reinterpret_cast<const float4*>(last_w + j));
            float4 w1 = __ldg(reinterpret_cast<const float4*>(last_w + 128 + j));
            float4 w2 = __ldg(reinterpret_cast<const float4*>(last_w + 256 + j));
            a0 += o.x * w0.x + o.y * w0.y + o.z * w0.z + o.w * w0.w;
            a1 += o.x * w1.x + o.y * w1.y + o.z * w1.z + o.w * w1.w;
            a2 += o.x * w2.x + o.y * w2.y + o.z * w2.z + o.w * w2.w;
        }
        long long gp = (long long)(p0 + p) * 3;
        outG[gp + 0] = phys[gp + 0] + a0;
        outG[gp + 1] = phys[gp + 1] + a1;
        outG[gp + 2] = phys[gp + 2] + a2;
    }
}

// ---------------------------------------------------------------------------
extern "C" void kernel_launch(void* const* d_in, const int* in_sizes, int n_in,
                              void* d_out, int out_size)
{
    const float* phys      = (const float*)d_in[0];
    const float* net       = (const float*)d_in[1];
    const float* tau       = (const float*)d_in[2];
    const float* vec_g[4]  = {(const float*)d_in[3], (const float*)d_in[4],
                              (const float*)d_in[5], (const float*)d_in[6]};
    const float* tau_g[4]  = {(const float*)d_in[7], (const float*)d_in[8],
                              (const float*)d_in[9], (const float*)d_in[10]};
    const float* vec_pe_w  = (const float*)d_in[11];
    const float* tau_pe_w  = (const float*)d_in[12];
    const float* tau_pe_b  = (const float*)d_in[13];
    const float* vec_scale = (const float*)d_in[14];
    const float* vec_map_w = (const float*)d_in[15];
    const float* tau_mlp_w = (const float*)d_in[16];
    const float* vec_mlp_w = (const float*)d_in[17];
    const float* tau_params= (const float*)d_in[18];
    const float* last_w    = (const float*)d_in[19];
    float* out = (float*)d_out;

    transpose_all<<<4624, 256>>>(vec_g[0], tau_g[0], vec_g[1], tau_g[1],
                                 vec_g[2], tau_g[2], vec_g[3], tau_g[3]);
    conv_weights<<<96, 256>>>(vec_map_w, tau_mlp_w, vec_mlp_w);

    cudaFuncSetAttribute(fused_kernel, cudaFuncAttributeMaxDynamicSharedMemorySize, 88576);
    fused_kernel<<<8192, NTH, 88576>>>(phys, net, tau,
                                       vec_pe_w, tau_pe_w, tau_pe_b, vec_scale,
                                       tau_params, last_w, out);
}

// round 8
// speedup vs baseline: 1.7930x; 1.1699x over previous
#include <cuda_runtime.h>
#include <cuda_bf16.h>
#include <cstdint>

#define NTH 256
#define BP  64

// Combined channel-last bf16 grids: levels S=16,32,64,96, 32 channels each
// voxel offsets: 0, 4096, 36864, 299008 ; total 1183744 voxels
#define TOT_VOX 1183744
__device__ __align__(16) __nv_bfloat16 g_comb[(size_t)TOT_VOX * 32];
// 6 weight matrices pre-converted to bf16, row stride 136 (smem-ready layout)
// order: vec_map0, vec_map1, tau_mlp, vec_mlp0, vec_mlp1, vec_mlp2
__device__ __align__(16) __nv_bfloat16 g_wbf[6 * 128 * 136];

// ---------------------------------------------------------------------------
// Prolog A: (C,S,S,S) fp32 vec+tau -> channel-last bf16 combined (all levels)
// ---------------------------------------------------------------------------
__global__ void transpose_all(const float* __restrict__ v0, const float* __restrict__ t0,
                              const float* __restrict__ v1, const float* __restrict__ t1,
                              const float* __restrict__ v2, const float* __restrict__ t2,
                              const float* __restrict__ v3, const float* __restrict__ t3)
{
    __shared__ float tile[32][257];
    const int b = blockIdx.x;
    const float* vec; const float* tau; int vol; long long outBase; int vbase;
    if (b < 16)        { vec = v0; tau = t0; vol = 4096;   outBase = 0LL;           vbase = b * 256; }
    else if (b < 144)  { vec = v1; tau = t1; vol = 32768;  outBase = 4096LL * 32;   vbase = (b - 16) * 256; }
    else if (b < 1168) { vec = v2; tau = t2; vol = 262144; outBase = 36864LL * 32;  vbase = (b - 144) * 256; }
    else               { vec = v3; tau = t3; vol = 884736; outBase = 299008LL * 32; vbase = (b - 1168) * 256; }

    const int tid = threadIdx.x;
    for (int i = tid; i < 32 * 256; i += 256) {
        int ch = i >> 8, vl = i & 255, v = vbase + vl;
        float val = 0.f;
        if (v < vol)
            val = (ch < 16) ? vec[(size_t)ch * vol + v]
                            : tau[(size_t)(ch - 16) * vol + v];
        tile[ch][vl] = val;
    }
    __syncthreads();
    __nv_bfloat16* out = g_comb + outBase;
    for (int i = tid; i < 16 * 256; i += 256) {
        int vl = i >> 4, cp = i & 15, v = vbase + vl;
        if (v < vol) {
            __nv_bfloat162 val = __floats2bfloat162_rn(tile[2 * cp][vl], tile[2 * cp + 1][vl]);
            *reinterpret_cast<__nv_bfloat162*>(out + (size_t)v * 32 + 2 * cp) = val;
        }
    }
}

// ---------------------------------------------------------------------------
// Prolog B: convert 6 weight matrices fp32 -> bf16 stride-136
// ---------------------------------------------------------------------------
__global__ void conv_weights(const float* __restrict__ vec_map_w,
                             const float* __restrict__ tau_mlp_w,
                             const float* __restrict__ vec_mlp_w)
{
    int i = blockIdx.x * 256 + threadIdx.x;          // 0 .. 6*128*32-1
    if (i >= 6 * 128 * 32) return;
    int mat = i >> 12;
    int r   = (i >> 5) & 127;
    int c4  = (i & 31) * 4;
    const float* src = (mat == 0) ? vec_map_w
                     : (mat == 1) ? vec_map_w + 16384
                     : (mat == 2) ? tau_mlp_w
                                  : vec_mlp_w + (mat - 3) * 16384;
    float4 f = *reinterpret_cast<const float4*>(src + r * 128 + c4);
    __nv_bfloat16* dst = g_wbf + (size_t)mat * 128 * 136 + r * 136 + c4;
    *reinterpret_cast<__nv_bfloat162*>(dst)     = __floats2bfloat162_rn(f.x, f.y);
    *reinterpret_cast<__nv_bfloat162*>(dst + 2) = __floats2bfloat162_rn(f.z, f.w);
}

// ---------------------------------------------------------------------------
// Math helpers
// ---------------------------------------------------------------------------
__device__ __forceinline__ float silu_f(float x) {
    return x * __fdividef(1.f, 1.f + __expf(-x));
}
__device__ __forceinline__ float tanh_f(float x) {
    float ax = fabsf(x);
    if (ax < 0.25f) {
        float x2 = x * x;
        return x * (1.f + x2 * (-0.333333333f + x2 * (0.133333333f - 0.0539682540f * x2)));
    }
    float e = __expf(2.f * x);
    return 1.f - __fdividef(2.f, e + 1.f);
}

__device__ __forceinline__ void accum8(float* acc, uint4 q, float w) {
    float2 f;
    f = __bfloat1622float2(*reinterpret_cast<__nv_bfloat162*>(&q.x));
    acc[0] = fmaf(w, f.x, acc[0]); acc[1] = fmaf(w, f.y, acc[1]);
    f = __bfloat1622float2(*reinterpret_cast<__nv_bfloat162*>(&q.y));
    acc[2] = fmaf(w, f.x, acc[2]); acc[3] = fmaf(w, f.y, acc[3]);
    f = __bfloat1622float2(*reinterpret_cast<__nv_bfloat162*>(&q.z));
    acc[4] = fmaf(w, f.x, acc[4]); acc[5] = fmaf(w, f.y, acc[5]);
    f = __bfloat1622float2(*reinterpret_cast<__nv_bfloat162*>(&q.w));
    acc[6] = fmaf(w, f.x, acc[6]); acc[7] = fmaf(w, f.y, acc[7]);
}

// Cooperative trilinear sample: 4 lanes per point, lane owns 16B chunk ck of
// each 64B voxel. ck 0,1 -> vec channels; ck 2,3 -> tau channels.
template<int S>
__device__ __forceinline__ void sample_coop(long long voxOff, int lvlBase,
                                            float cx, float cy, float cz,
                                            int pt, int ck,
                                            __nv_bfloat16* sA, __nv_bfloat16* sT)
{
    const float s1 = (float)(S - 1);
    float px = fminf(fmaxf((cx + 1.f) * 0.5f * s1, 0.f), s1);
    float py = fminf(fmaxf((cy + 1.f) * 0.5f * s1, 0.f), s1);
    float pz = fminf(fmaxf((cz + 1.f) * 0.5f * s1, 0.f), s1);
    int x0 = (int)px, y0 = (int)py, z0 = (int)pz;
    float wx = px - (float)x0, wy = py - (float)y0, wz = pz - (float)z0;
    int x1 = min(x0 + 1, S - 1), y1 = min(y0 + 1, S - 1), z1 = min(z0 + 1, S - 1);

    const __nv_bfloat16* g = g_comb + voxOff * 32 + ck * 8;
    float acc[8];
#pragma unroll
    for (int i = 0; i < 8; i++) acc[i] = 0.f;

    const int   xs[2]  = {x0, x1}, ys[2] = {y0, y1}, zs[2] = {z0, z1};
    const float wxs[2] = {1.f - wx, wx}, wys[2] = {1.f - wy, wy}, wzs[2] = {1.f - wz, wz};
#pragma unroll
    for (int a = 0; a < 2; a++)
#pragma unroll
        for (int b = 0; b < 2; b++)
#pragma unroll
            for (int c = 0; c < 2; c++) {
                float w = wzs[a] * wys[b] * wxs[c];
                uint4 q = *reinterpret_cast<const uint4*>(
                    g + (size_t)((zs[a] * S + ys[b]) * S + xs[c]) * 32);
                accum8(acc, q, w);
            }
    __nv_bfloat16* dst = (ck < 2) ? sA : sT;
    const int cb = lvlBase + (ck & 1) * 8;
#pragma unroll
    for (int c = 0; c < 8; c += 2)
        *reinterpret_cast<__nv_bfloat162*>(&dst[pt * 136 + cb + c]) =
            __floats2bfloat162_rn(silu_f(acc[c]), silu_f(acc[c + 1]));
}

// Cooperative bf16 weight copy (global, already stride-136) -> smem
__device__ __forceinline__ void load_w(int mat, __nv_bfloat16* sW)
{
    const uint4* src = reinterpret_cast<const uint4*>(g_wbf + (size_t)mat * 128 * 136);
    uint4* dst = reinterpret_cast<uint4*>(sW);
    const int tid = threadIdx.x;
#pragma unroll
    for (int i = 0; i < 8; i++)
        dst[tid + i * NTH] = src[tid + i * NTH];
    int i8 = tid + 8 * NTH;
    if (i8 < 2176) dst[i8] = src[i8];
}

// ---------------------------------------------------------------------------
// mma.sync helpers
// ---------------------------------------------------------------------------
__device__ __forceinline__ void ldm4(uint32_t& r0, uint32_t& r1, uint32_t& r2, uint32_t& r3,
                                     uint32_t addr)
{
    asm volatile("ldmatrix.sync.aligned.m8n8.x4.shared.b16 {%0,%1,%2,%3}, [%4];\n"
                 : "=r"(r0), "=r"(r1), "=r"(r2), "=r"(r3) : "r"(addr));
}
__device__ __forceinline__ void mma16816(float* c, const uint32_t* a, const uint32_t* b)
{
    asm volatile(
        "mma.sync.aligned.m16n8k16.row.col.f32.bf16.bf16.f32 "
        "{%0,%1,%2,%3},{%4,%5,%6,%7},{%8,%9},{%0,%1,%2,%3};\n"
        : "+f"(c[0]), "+f"(c[1]), "+f"(c[2]), "+f"(c[3])
        : "r"(a[0]), "r"(a[1]), "r"(a[2]), "r"(a[3]), "r"(b[0]), "r"(b[1]));
}

// C[p][j] = sum_k A[p][k] * W[j][k], 64x128x128, bf16 in / fp32 acc.
// 8 warps: warp tile 32(m) x 32(n); frag grid 2 x 4 of m16n8k16.
__device__ __forceinline__ void gemm64(const __nv_bfloat16* A, const __nv_bfloat16* W,
                                       float (&acc)[2][4][4], int lane, int m0, int n0)
{
#pragma unroll
    for (int mi = 0; mi < 2; mi++)
#pragma unroll
        for (int ni = 0; ni < 4; ni++)
#pragma unroll
            for (int t = 0; t < 4; t++) acc[mi][ni][t] = 0.f;

    uint32_t aBase = (uint32_t)__cvta_generic_to_shared(A)
                   + (uint32_t)((m0 + (lane & 15)) * 272 + (lane >> 4) * 16);
    uint32_t bBase = (uint32_t)__cvta_generic_to_shared(W)
                   + (uint32_t)((n0 + (lane & 7) + ((lane >> 4) << 3)) * 272
                                + ((lane >> 3) & 1) * 16);
#pragma unroll
    for (int k = 0; k < 8; k++) {
        uint32_t a[2][4];
        ldm4(a[0][0], a[0][1], a[0][2], a[0][3], aBase + k * 32);
        ldm4(a[1][0], a[1][1], a[1][2], a[1][3], aBase + 16 * 272 + k * 32);
        uint32_t b[4][2];
#pragma unroll
        for (int t = 0; t < 2; t++) {
            uint32_t r0, r1, r2, r3;
            ldm4(r0, r1, r2, r3, bBase + t * (16 * 272) + k * 32);
            b[2 * t][0] = r0; b[2 * t][1] = r1;
            b[2 * t + 1][0] = r2; b[2 * t + 1][1] = r3;
        }
#pragma unroll
        for (int mi = 0; mi < 2; mi++)
#pragma unroll
            for (int ni = 0; ni < 4; ni++)
                mma16816(acc[mi][ni], a[mi], b[ni]);
    }
}

// ---------------------------------------------------------------------------
// Fused main kernel: 64 points per block, 256 threads, 2 CTAs/SM
// ---------------------------------------------------------------------------
__global__ void __launch_bounds__(NTH, 2)
fused_kernel(const float* __restrict__ phys, const float* __restrict__ net,
             const float* __restrict__ tauIn,
             const float* __restrict__ vec_pe_w, const float* __restrict__ tau_pe_w,
             const float* __restrict__ tau_pe_b, const float* __restrict__ vec_scale,
             const float* __restrict__ tau_params,
             const float* __restrict__ last_w, float* __restrict__ outG)
{
    extern __shared__ char smem[];
    __nv_bfloat16* sA0 = (__nv_bfloat16*)(smem);            // 17408 B
    __nv_bfloat16* sA1 = (__nv_bfloat16*)(smem + 17408);    // 17408 B
    __nv_bfloat16* sT  = (__nv_bfloat16*)(smem + 34816);    // 17408 B
    __nv_bfloat16* sW  = (__nv_bfloat16*)(smem + 52224);    // 34816 B
    float* sTau   = (float*)(smem + 87040);                 // 256 B
    float* sScale = (float*)(smem + 87296);                 // 512 B
    float* sCx    = (float*)(smem + 87808);                 // 256 B
    float* sCy    = (float*)(smem + 88064);                 // 256 B
    float* sCz    = (float*)(smem + 88320);                 // end 88576
    float* sOutF  = (float*)(smem);                         // 64*132*4 (reuse)

    const int tid = threadIdx.x;
    const int p0  = blockIdx.x * BP;

    if (tid < BP) {
        int gp = p0 + tid;
        sCx[tid]  = net[gp * 3 + 0];
        sCy[tid]  = net[gp * 3 + 1];
        sCz[tid]  = net[gp * 3 + 2];
        sTau[tid] = tauIn[gp];
    }
    if (tid < 128) sScale[tid] = vec_scale[tid];
    __syncthreads();

    // ---- sampling: 4 lanes cooperate per point, all threads do all levels ----
    {
        int pt = tid >> 2, ck = tid & 3;
        float cx = sCx[pt], cy = sCy[pt], cz = sCz[pt];
        sample_coop<16>(0LL,      0,  cx, cy, cz, pt, ck, sA0, sT);
        sample_coop<32>(4096LL,   16, cx, cy, cz, pt, ck, sA0, sT);
        sample_coop<64>(36864LL,  32, cx, cy, cz, pt, ck, sA0, sT);
        sample_coop<96>(299008LL, 48, cx, cy, cz, pt, ck, sA0, sT);
    }
    // ---- FFM features ----
#pragma unroll 4
    for (int i = tid; i < 64 * 64; i += NTH) {
        int p = i >> 6, j = i & 63;
        float d = sCx[p] * vec_pe_w[j * 3] + sCy[p] * vec_pe_w[j * 3 + 1]
                + sCz[p] * vec_pe_w[j * 3 + 2];
        sA0[p * 136 + 64 + j] = __float2bfloat16(__sinf(d));
    }
#pragma unroll 4
    for (int i = tid; i < 64 * 64; i += NTH) {
        int p = i >> 6, j = i & 63;
        float d = sCx[p] * tau_pe_w[j * 3] + sCy[p] * tau_pe_w[j * 3 + 1]
                + sCz[p] * tau_pe_w[j * 3 + 2] + tau_pe_b[j];
        sT[p * 136 + 64 + j] = __float2bfloat16(__sinf(d));
    }
    __syncthreads();

    const int lane = tid & 31, wid = tid >> 5;
    const int m0 = (wid & 1) * 32, n0 = (wid >> 1) * 32;
    float acc[2][4][4];
    float outF[2][4][4];

    // ---- vec_map layer 0 ----
    load_w(0, sW);
    __syncthreads();
    gemm64(sA0, sW, acc, lane, m0, n0);
#pragma unroll
    for (int mi = 0; mi < 2; mi++)
#pragma unroll
        for (int ni = 0; ni < 4; ni++)
#pragma unroll
            for (int hi = 0; hi < 2; hi++) {
                int p = m0 + mi * 16 + (lane >> 2) + hi * 8;
                int j = n0 + ni * 8 + (lane & 3) * 2;
                *reinterpret_cast<__nv_bfloat162*>(&sA1[p * 136 + j]) =
                    __floats2bfloat162_rn(silu_f(acc[mi][ni][hi * 2]),
                                          silu_f(acc[mi][ni][hi * 2 + 1]));
            }
    __syncthreads();

    // ---- vec_map layer 1 + out init: out = tanh(tau*scale*silu(h)) ----
    load_w(1, sW);
    __syncthreads();
    gemm64(sA1, sW, acc, lane, m0, n0);
#pragma unroll
    for (int mi = 0; mi < 2; mi++)
#pragma unroll
        for (int ni = 0; ni < 4; ni++)
#pragma unroll
            for (int hi = 0; hi < 2; hi++) {
                int p = m0 + mi * 16 + (lane >> 2) + hi * 8;
                int j = n0 + ni * 8 + (lane & 3) * 2;
                float tp = sTau[p];
                float s0 = sScale[j], s1 = sScale[j + 1];
                float o0 = tanh_f(tp * s0 * silu_f(acc[mi][ni][hi * 2]));
                float o1 = tanh_f(tp * s1 * silu_f(acc[mi][ni][hi * 2 + 1]));
                outF[mi][ni][hi * 2]     = o0;
                outF[mi][ni][hi * 2 + 1] = o1;
                *reinterpret_cast<__nv_bfloat162*>(&sA0[p * 136 + j]) =
                    __floats2bfloat162_rn(o0, o1);
            }
    __syncthreads();

    // ---- tau path: ttt = tauF @ tau_mlp_w^T (bf16 back into sT) ----
    load_w(2, sW);
    __syncthreads();
    gemm64(sT, sW, acc, lane, m0, n0);
    __syncthreads();
#pragma unroll
    for (int mi = 0; mi < 2; mi++)
#pragma unroll
        for (int ni = 0; ni < 4; ni++)
#pragma unroll
            for (int hi = 0; hi < 2; hi++) {
                int p = m0 + mi * 16 + (lane >> 2) + hi * 8;
                int j = n0 + ni * 8 + (lane & 3) * 2;
                *reinterpret_cast<__nv_bfloat162*>(&sT[p * 136 + j]) =
                    __floats2bfloat162_rn(acc[mi][ni][hi * 2], acc[mi][ni][hi * 2 + 1]);
            }
    __syncthreads();

    // ---- 3 residual layers ----
#pragma unroll 1
    for (int idx = 0; idx < 3; idx++) {
        load_w(3 + idx, sW);
        __syncthreads();
        const __nv_bfloat16* Abuf = (idx & 1) ? sA1 : sA0;
        __nv_bfloat16*       Bout = (idx & 1) ? sA0 : sA1;
        gemm64(Abuf, sW, acc, lane, m0, n0);
        const float* tpar = tau_params + idx * 128;
#pragma unroll
        for (int mi = 0; mi < 2; mi++)
#pragma unroll
            for (int ni = 0; ni < 4; ni++)
#pragma unroll
                for (int hi = 0; hi < 2; hi++) {
                    int p = m0 + mi * 16 + (lane >> 2) + hi * 8;
                    int j = n0 + ni * 8 + (lane & 3) * 2;
                    float h0 = acc[mi][ni][hi * 2], h1 = acc[mi][ni][hi * 2 + 1];
                    if (idx == 0) {
                        float2 t = __bfloat1622float2(
                            *reinterpret_cast<__nv_bfloat162*>(&sT[p * 136 + j]));
                        h0 *= t.x; h1 *= t.y;
                    }
                    float tp = sTau[p];
                    float tt0 = tanh_f(tp * __ldg(&tpar[j]));
                    float tt1 = tanh_f(tp * __ldg(&tpar[j + 1]));
                    float o0 = outF[mi][ni][hi * 2]     + tt0 * silu_f(h0);
                    float o1 = outF[mi][ni][hi * 2 + 1] + tt1 * silu_f(h1);
                    outF[mi][ni][hi * 2]     = o0;
                    outF[mi][ni][hi * 2 + 1] = o1;
                    if (idx < 2)
                        *reinterpret_cast<__nv_bfloat162*>(&Bout[p * 136 + j]) =
                            __floats2bfloat162_rn(o0, o1);
                }
        __syncthreads();
    }

    // ---- spill fp32 out to smem (reuses sA0/sA1 region) ----
#pragma unroll
    for (int mi = 0; mi < 2; mi++)
#pragma unroll
        for (int ni = 0; ni < 4; ni++)
#pragma unroll
            for (int hi = 0; hi < 2; hi++) {
                int p = m0 + mi * 16 + (lane >> 2) + hi * 8;
                int j = n0 + ni * 8 + (lane & 3) * 2;
                *reinterpret_cast<float2*>(&sOutF[p * 132 + j]) =
                    make_float2(outF[mi][ni][hi * 2], outF[mi][ni][hi * 2 + 1]);
            }
    __syncthreads();

    // ---- head: res = phys + out @ last_w^T ----
    if (tid < BP) {
        int p = tid;
        float a0 = 0.f, a1 = 0.f, a2 = 0.f;
#pragma unroll 8
        for (int j = 0; j < 128; j += 4) {
            float4 o  = *reinterpret_cast<float4*>(&sOutF[p * 132 + j]);
            float4 w0 = __ldg(reinterpret_cast<const float4*>(last_w + j));
            float4 w1 = __ldg(reinterpret_cast<const float4*>(last_w + 128 + j));
            float4 w2 = __ldg(reinterpret_cast<const float4*>(last_w + 256 + j));
            a0 += o.x * w0.x + o.y * w0.y + o.z * w0.z + o.w * w0.w;
            a1 += o.x * w1.x + o.y * w1.y + o.z * w1.z + o.w * w1.w;
            a2 += o.x * w2.x + o.y * w2.y + o.z * w2.z + o.w * w2.w;
        }
        long long gp = (long long)(p0 + p) * 3;
        outG[gp + 0] = phys[gp + 0] + a0;
        outG[gp + 1] = phys[gp + 1] + a1;
        outG[gp + 2] = phys[gp + 2] + a2;
    }
}

// ---------------------------------------------------------------------------
extern "C" void kernel_launch(void* const* d_in, const int* in_sizes, int n_in,
                              void* d_out, int out_size)
{
    const float* phys      = (const float*)d_in[0];
    const float* net       = (const float*)d_in[1];
    const float* tau       = (const float*)d_in[2];
    const float* vec_g[4]  = {(const float*)d_in[3], (const float*)d_in[4],
                              (const float*)d_in[5], (const float*)d_in[6]};
    const float* tau_g[4]  = {(const float*)d_in[7], (const float*)d_in[8],
                              (const float*)d_in[9], (const float*)d_in[10]};
    const float* vec_pe_w  = (const float*)d_in[11];
    const float* tau_pe_w  = (const float*)d_in[12];
    const float* tau_pe_b  = (const float*)d_in[13];
    const float* vec_scale = (const float*)d_in[14];
    const float* vec_map_w = (const float*)d_in[15];
    const float* tau_mlp_w = (const float*)d_in[16];
    const float* vec_mlp_w = (const float*)d_in[17];
    const float* tau_params= (const float*)d_in[18];
    const float* last_w    = (const float*)d_in[19];
    float* out = (float*)d_out;

    transpose_all<<<4624, 256>>>(vec_g[0], tau_g[0], vec_g[1], tau_g[1],
                                 vec_g[2], tau_g[2], vec_g[3], tau_g[3]);
    conv_weights<<<96, 256>>>(vec_map_w, tau_mlp_w, vec_mlp_w);

    cudaFuncSetAttribute(fused_kernel, cudaFuncAttributeMaxDynamicSharedMemorySize, 88576);
    fused_kernel<<<8192, NTH, 88576>>>(phys, net, tau,
                                       vec_pe_w, tau_pe_w, tau_pe_b, vec_scale,
                                       tau_params, last_w, out);
}

// round 11
// speedup vs baseline: 1.8995x; 1.0594x over previous
#include <cuda_runtime.h>
#include <cuda_bf16.h>
#include <cstdint>

#define NTH 256
#define BP  64

// Combined channel-last bf16 grids: levels S=16,32,64,96, 32 channels each
// voxel offsets: 0, 4096, 36864, 299008 ; total 1183744 voxels
#define TOT_VOX 1183744
__device__ __align__(16) __nv_bfloat16 g_comb[(size_t)TOT_VOX * 32];
// 6 weight matrices pre-converted to bf16, row stride 136 (smem-ready layout)
// order: vec_map0, vec_map1, tau_mlp, vec_mlp0, vec_mlp1, vec_mlp2
__device__ __align__(16) __nv_bfloat16 g_wbf[6 * 128 * 136];

// ---------------------------------------------------------------------------
// Prolog: grid transpose (blocks 0..4623) + weight conversion (blocks 4624+)
// ---------------------------------------------------------------------------
__global__ void prolog_all(const float* __restrict__ v0, const float* __restrict__ t0,
                           const float* __restrict__ v1, const float* __restrict__ t1,
                           const float* __restrict__ v2, const float* __restrict__ t2,
                           const float* __restrict__ v3, const float* __restrict__ t3,
                           const float* __restrict__ vec_map_w,
                           const float* __restrict__ tau_mlp_w,
                           const float* __restrict__ vec_mlp_w)
{
    const int b = blockIdx.x;
    const int tid = threadIdx.x;

    if (b >= 4624) {  // weight conversion: 96 blocks * 256 threads = 6*128*32
        int i = (b - 4624) * 256 + tid;
        if (i >= 6 * 128 * 32) return;
        int mat = i >> 12;
        int r   = (i >> 5) & 127;
        int c4  = (i & 31) * 4;
        const float* src = (mat == 0) ? vec_map_w
                         : (mat == 1) ? vec_map_w + 16384
                         : (mat == 2) ? tau_mlp_w
                                      : vec_mlp_w + (mat - 3) * 16384;
        float4 f = *reinterpret_cast<const float4*>(src + r * 128 + c4);
        __nv_bfloat16* dst = g_wbf + (size_t)mat * 128 * 136 + r * 136 + c4;
        *reinterpret_cast<__nv_bfloat162*>(dst)     = __floats2bfloat162_rn(f.x, f.y);
        *reinterpret_cast<__nv_bfloat162*>(dst + 2) = __floats2bfloat162_rn(f.z, f.w);
        return;
    }

    __shared__ float tile[32][257];
    const float* vec; const float* tau; int vol; long long outBase; int vbase;
    if (b < 16)        { vec = v0; tau = t0; vol = 4096;   outBase = 0LL;           vbase = b * 256; }
    else if (b < 144)  { vec = v1; tau = t1; vol = 32768;  outBase = 4096LL * 32;   vbase = (b - 16) * 256; }
    else if (b < 1168) { vec = v2; tau = t2; vol = 262144; outBase = 36864LL * 32;  vbase = (b - 144) * 256; }
    else               { vec = v3; tau = t3; vol = 884736; outBase = 299008LL * 32; vbase = (b - 1168) * 256; }

    for (int i = tid; i < 32 * 256; i += 256) {
        int ch = i >> 8, vl = i & 255, v = vbase + vl;
        float val = 0.f;
        if (v < vol)
            val = (ch < 16) ? vec[(size_t)ch * vol + v]
                            : tau[(size_t)(ch - 16) * vol + v];
        tile[ch][vl] = val;
    }
    __syncthreads();
    __nv_bfloat16* out = g_comb + outBase;
    for (int i = tid; i < 16 * 256; i += 256) {
        int vl = i >> 4, cp = i & 15, v = vbase + vl;
        if (v < vol) {
            __nv_bfloat162 val = __floats2bfloat162_rn(tile[2 * cp][vl], tile[2 * cp + 1][vl]);
            *reinterpret_cast<__nv_bfloat162*>(out + (size_t)v * 32 + 2 * cp) = val;
        }
    }
}

// ---------------------------------------------------------------------------
// Math helpers
// ---------------------------------------------------------------------------
__device__ __forceinline__ float silu_f(float x) {
    return x * __fdividef(1.f, 1.f + __expf(-x));
}
__device__ __forceinline__ float tanh_f(float x) {
    float ax = fabsf(x);
    if (ax < 0.25f) {
        float x2 = x * x;
        return x * (1.f + x2 * (-0.333333333f + x2 * (0.133333333f - 0.0539682540f * x2)));
    }
    float e = __expf(2.f * x);
    return 1.f - __fdividef(2.f, e + 1.f);
}

__device__ __forceinline__ void accum8(float* acc, uint4 q, float w) {
    float2 f;
    f = __bfloat1622float2(*reinterpret_cast<__nv_bfloat162*>(&q.x));
    acc[0] = fmaf(w, f.x, acc[0]); acc[1] = fmaf(w, f.y, acc[1]);
    f = __bfloat1622float2(*reinterpret_cast<__nv_bfloat162*>(&q.y));
    acc[2] = fmaf(w, f.x, acc[2]); acc[3] = fmaf(w, f.y, acc[3]);
    f = __bfloat1622float2(*reinterpret_cast<__nv_bfloat162*>(&q.z));
    acc[4] = fmaf(w, f.x, acc[4]); acc[5] = fmaf(w, f.y, acc[5]);
    f = __bfloat1622float2(*reinterpret_cast<__nv_bfloat162*>(&q.w));
    acc[6] = fmaf(w, f.x, acc[6]); acc[7] = fmaf(w, f.y, acc[7]);
}

// Cooperative trilinear sample: 4 lanes per point, lane owns 16B chunk ck of
// each 64B voxel. ck 0,1 -> vec channels; ck 2,3 -> tau channels.
template<int S>
__device__ __forceinline__ void sample_coop(long long voxOff, int lvlBase,
                                            float cx, float cy, float cz,
                                            int pt, int ck,
                                            __nv_bfloat16* sF, __nv_bfloat16* sT)
{
    const float s1 = (float)(S - 1);
    float px = fminf(fmaxf((cx + 1.f) * 0.5f * s1, 0.f), s1);
    float py = fminf(fmaxf((cy + 1.f) * 0.5f * s1, 0.f), s1);
    float pz = fminf(fmaxf((cz + 1.f) * 0.5f * s1, 0.f), s1);
    int x0 = (int)px, y0 = (int)py, z0 = (int)pz;
    float wx = px - (float)x0, wy = py - (float)y0, wz = pz - (float)z0;
    int x1 = min(x0 + 1, S - 1), y1 = min(y0 + 1, S - 1), z1 = min(z0 + 1, S - 1);

    const __nv_bfloat16* g = g_comb + voxOff * 32 + ck * 8;
    float acc[8];
#pragma unroll
    for (int i = 0; i < 8; i++) acc[i] = 0.f;

    const int   xs[2]  = {x0, x1}, ys[2] = {y0, y1}, zs[2] = {z0, z1};
    const float wxs[2] = {1.f - wx, wx}, wys[2] = {1.f - wy, wy}, wzs[2] = {1.f - wz, wz};
#pragma unroll
    for (int a = 0; a < 2; a++)
#pragma unroll
        for (int b = 0; b < 2; b++)
#pragma unroll
            for (int c = 0; c < 2; c++) {
                float w = wzs[a] * wys[b] * wxs[c];
                uint4 q = *reinterpret_cast<const uint4*>(
                    g + (size_t)((zs[a] * S + ys[b]) * S + xs[c]) * 32);
                accum8(acc, q, w);
            }
    __nv_bfloat16* dst = (ck < 2) ? sF : sT;
    const int cb = lvlBase + (ck & 1) * 8;
#pragma unroll
    for (int c = 0; c < 8; c += 2)
        *reinterpret_cast<__nv_bfloat162*>(&dst[pt * 136 + cb + c]) =
            __floats2bfloat162_rn(silu_f(acc[c]), silu_f(acc[c + 1]));
}

// ---------------------------------------------------------------------------
// cp.async weight prefetch (global bf16 stride-136 -> smem), one commit group
// ---------------------------------------------------------------------------
__device__ __forceinline__ void load_w_async(int mat, __nv_bfloat16* sW)
{
    const uint4* src = reinterpret_cast<const uint4*>(g_wbf + (size_t)mat * 128 * 136);
    uint32_t dst = (uint32_t)__cvta_generic_to_shared(sW);
    const int tid = threadIdx.x;
#pragma unroll
    for (int i = 0; i < 8; i++)
        asm volatile("cp.async.cg.shared.global [%0], [%1], 16;\n"
                     :: "r"(dst + (tid + i * NTH) * 16), "l"(src + tid + i * NTH));
    int i8 = tid + 8 * NTH;
    if (i8 < 2176)
        asm volatile("cp.async.cg.shared.global [%0], [%1], 16;\n"
                     :: "r"(dst + i8 * 16), "l"(src + i8));
    asm volatile("cp.async.commit_group;\n");
}
#define CP_WAIT0() asm volatile("cp.async.wait_group 0;\n" ::: "memory")

// ---------------------------------------------------------------------------
// mma.sync helpers
// ---------------------------------------------------------------------------
__device__ __forceinline__ void ldm4(uint32_t& r0, uint32_t& r1, uint32_t& r2, uint32_t& r3,
                                     uint32_t addr)
{
    asm volatile("ldmatrix.sync.aligned.m8n8.x4.shared.b16 {%0,%1,%2,%3}, [%4];\n"
                 : "=r"(r0), "=r"(r1), "=r"(r2), "=r"(r3) : "r"(addr));
}
__device__ __forceinline__ void mma16816(float* c, const uint32_t* a, const uint32_t* b)
{
    asm volatile(
        "mma.sync.aligned.m16n8k16.row.col.f32.bf16.bf16.f32 "
        "{%0,%1,%2,%3},{%4,%5,%6,%7},{%8,%9},{%0,%1,%2,%3};\n"
        : "+f"(c[0]), "+f"(c[1]), "+f"(c[2]), "+f"(c[3])
        : "r"(a[0]), "r"(a[1]), "r"(a[2]), "r"(a[3]), "r"(b[0]), "r"(b[1]));
}

// C[p][j] = sum_k A[p][k] * W[j][k], 64x128x128, bf16 in / fp32 acc.
// 8 warps: warp tile 32(m) x 32(n); frag grid 2 x 4 of m16n8k16.
__device__ __forceinline__ void gemm64(const __nv_bfloat16* A, const __nv_bfloat16* W,
                                       float (&acc)[2][4][4], int lane, int m0, int n0)
{
#pragma unroll
    for (int mi = 0; mi < 2; mi++)
#pragma unroll
        for (int ni = 0; ni < 4; ni++)
#pragma unroll
            for (int t = 0; t < 4; t++) acc[mi][ni][t] = 0.f;

    uint32_t aBase = (uint32_t)__cvta_generic_to_shared(A)
                   + (uint32_t)((m0 + (lane & 15)) * 272 + (lane >> 4) * 16);
    uint32_t bBase = (uint32_t)__cvta_generic_to_shared(W)
                   + (uint32_t)((n0 + (lane & 7) + ((lane >> 4) << 3)) * 272
                                + ((lane >> 3) & 1) * 16);
#pragma unroll
    for (int k = 0; k < 8; k++) {
        uint32_t a[2][4];
        ldm4(a[0][0], a[0][1], a[0][2], a[0][3], aBase + k * 32);
        ldm4(a[1][0], a[1][1], a[1][2], a[1][3], aBase + 16 * 272 + k * 32);
        uint32_t b[4][2];
#pragma unroll
        for (int t = 0; t < 2; t++) {
            uint32_t r0, r1, r2, r3;
            ldm4(r0, r1, r2, r3, bBase + t * (16 * 272) + k * 32);
            b[2 * t][0] = r0; b[2 * t][1] = r1;
            b[2 * t + 1][0] = r2; b[2 * t + 1][1] = r3;
        }
#pragma unroll
        for (int mi = 0; mi < 2; mi++)
#pragma unroll
            for (int ni = 0; ni < 4; ni++)
                mma16816(acc[mi][ni], a[mi], b[ni]);
    }
}

// ---------------------------------------------------------------------------
// Fused main kernel: 64 points / block, 256 threads, 2 CTAs/SM,
// double-buffered cp.async weights, in-place activation buffers.
// ---------------------------------------------------------------------------
__global__ void __launch_bounds__(NTH, 2)
fused_kernel(const float* __restrict__ phys, const float* __restrict__ net,
             const float* __restrict__ tauIn,
             const float* __restrict__ vec_pe_w, const float* __restrict__ tau_pe_w,
             const float* __restrict__ tau_pe_b, const float* __restrict__ vec_scale,
             const float* __restrict__ tau_params,
             const float* __restrict__ last_w, float* __restrict__ outG)
{
    extern __shared__ char smem[];
    __nv_bfloat16* sF  = (__nv_bfloat16*)(smem);            // 17408 B
    __nv_bfloat16* sT  = (__nv_bfloat16*)(smem + 17408);    // 17408 B
    __nv_bfloat16* sW0 = (__nv_bfloat16*)(smem + 34816);    // 34816 B
    __nv_bfloat16* sW1 = (__nv_bfloat16*)(smem + 69632);    // 34816 B
    float* sTau   = (float*)(smem + 104448);                // 256 B
    float* sScale = (float*)(smem + 104704);                // 512 B
    float* sCx    = (float*)(smem + 105216);                // 256 B
    float* sCy    = (float*)(smem + 105472);                // 256 B
    float* sCz    = (float*)(smem + 105728);                // end 105984
    float* sOutF  = (float*)(smem + 34816);                 // overlays sW0 (33792 B)

    const int tid = threadIdx.x;
    const int p0  = blockIdx.x * BP;

    // prefetch W0 (overlaps gather + FFM)
    load_w_async(0, sW0);

    if (tid < BP) {
        int gp = p0 + tid;
        sCx[tid]  = net[gp * 3 + 0];
        sCy[tid]  = net[gp * 3 + 1];
        sCz[tid]  = net[gp * 3 + 2];
        sTau[tid] = tauIn[gp];
    }
    if (tid < 128) sScale[tid] = vec_scale[tid];
    __syncthreads();

    // ---- sampling: 4 lanes cooperate per point ----
    {
        int pt = tid >> 2, ck = tid & 3;
        float cx = sCx[pt], cy = sCy[pt], cz = sCz[pt];
        sample_coop<16>(0LL,      0,  cx, cy, cz, pt, ck, sF, sT);
        sample_coop<32>(4096LL,   16, cx, cy, cz, pt, ck, sF, sT);
        sample_coop<64>(36864LL,  32, cx, cy, cz, pt, ck, sF, sT);
        sample_coop<96>(299008LL, 48, cx, cy, cz, pt, ck, sF, sT);
    }
    // ---- FFM features ----
#pragma unroll 4
    for (int i = tid; i < 64 * 64; i += NTH) {
        int p = i >> 6, j = i & 63;
        float d = sCx[p] * vec_pe_w[j * 3] + sCy[p] * vec_pe_w[j * 3 + 1]
                + sCz[p] * vec_pe_w[j * 3 + 2];
        sF[p * 136 + 64 + j] = __float2bfloat16(__sinf(d));
    }
#pragma unroll 4
    for (int i = tid; i < 64 * 64; i += NTH) {
        int p = i >> 6, j = i & 63;
        float d = sCx[p] * tau_pe_w[j * 3] + sCy[p] * tau_pe_w[j * 3 + 1]
                + sCz[p] * tau_pe_w[j * 3 + 2] + tau_pe_b[j];
        sT[p * 136 + 64 + j] = __float2bfloat16(__sinf(d));
    }
    CP_WAIT0();
    __syncthreads();

    const int lane = tid & 31, wid = tid >> 5;
    const int m0 = (wid & 1) * 32, n0 = (wid >> 1) * 32;
    float acc[2][4][4];
    float outF[2][4][4];

    // ---- vec_map layer 0 (W in sW0; prefetch W1) ----
    load_w_async(1, sW1);
    gemm64(sF, sW0, acc, lane, m0, n0);
    __syncthreads();   // all A reads done
#pragma unroll
    for (int mi = 0; mi < 2; mi++)
#pragma unroll
        for (int ni = 0; ni < 4; ni++)
#pragma unroll
            for (int hi = 0; hi < 2; hi++) {
                int p = m0 + mi * 16 + (lane >> 2) + hi * 8;
                int j = n0 + ni * 8 + (lane & 3) * 2;
                *reinterpret_cast<__nv_bfloat162*>(&sF[p * 136 + j]) =
                    __floats2bfloat162_rn(silu_f(acc[mi][ni][hi * 2]),
                                          silu_f(acc[mi][ni][hi * 2 + 1]));
            }
    CP_WAIT0();
    __syncthreads();

    // ---- vec_map layer 1 + out init (W in sW1; prefetch tau_mlp) ----
    load_w_async(2, sW0);
    gemm64(sF, sW1, acc, lane, m0, n0);
    __syncthreads();
#pragma unroll
    for (int mi = 0; mi < 2; mi++)
#pragma unroll
        for (int ni = 0; ni < 4; ni++)
#pragma unroll
            for (int hi = 0; hi < 2; hi++) {
                int p = m0 + mi * 16 + (lane >> 2) + hi * 8;
                int j = n0 + ni * 8 + (lane & 3) * 2;
                float tp = sTau[p];
                float s0 = sScale[j], s1 = sScale[j + 1];
                float o0 = tanh_f(tp * s0 * silu_f(acc[mi][ni][hi * 2]));
                float o1 = tanh_f(tp * s1 * silu_f(acc[mi][ni][hi * 2 + 1]));
                outF[mi][ni][hi * 2]     = o0;
                outF[mi][ni][hi * 2 + 1] = o1;
                *reinterpret_cast<__nv_bfloat162*>(&sF[p * 136 + j]) =
                    __floats2bfloat162_rn(o0, o1);
            }
    CP_WAIT0();
    __syncthreads();

    // ---- tau path (W in sW0; prefetch mlp0) ----
    load_w_async(3, sW1);
    gemm64(sT, sW0, acc, lane, m0, n0);
    __syncthreads();
#pragma unroll
    for (int mi = 0; mi < 2; mi++)
#pragma unroll
        for (int ni = 0; ni < 4; ni++)
#pragma unroll
            for (int hi = 0; hi < 2; hi++) {
                int p = m0 + mi * 16 + (lane >> 2) + hi * 8;
                int j = n0 + ni * 8 + (lane & 3) * 2;
                *reinterpret_cast<__nv_bfloat162*>(&sT[p * 136 + j]) =
                    __floats2bfloat162_rn(acc[mi][ni][hi * 2], acc[mi][ni][hi * 2 + 1]);
            }
    CP_WAIT0();
    __syncthreads();

    // ---- residual layer 0 (W in sW1; prefetch mlp1) ----
    load_w_async(4, sW0);
    gemm64(sF, sW1, acc, lane, m0, n0);
    __syncthreads();
    {
        const float* tpar = tau_params;
#pragma unroll
        for (int mi = 0; mi < 2; mi++)
#pragma unroll
            for (int ni = 0; ni < 4; ni++)
#pragma unroll
                for (int hi = 0; hi < 2; hi++) {
                    int p = m0 + mi * 16 + (lane >> 2) + hi * 8;
                    int j = n0 + ni * 8 + (lane & 3) * 2;
                    float2 t = __bfloat1622float2(
                        *reinterpret_cast<__nv_bfloat162*>(&sT[p * 136 + j]));
                    float h0 = acc[mi][ni][hi * 2] * t.x;
                    float h1 = acc[mi][ni][hi * 2 + 1] * t.y;
                    float tp = sTau[p];
                    float tt0 = tanh_f(tp * __ldg(&tpar[j]));
                    float tt1 = tanh_f(tp * __ldg(&tpar[j + 1]));
                    float o0 = outF[mi][ni][hi * 2]     + tt0 * silu_f(h0);
                    float o1 = outF[mi][ni][hi * 2 + 1] + tt1 * silu_f(h1);
                    outF[mi][ni][hi * 2]     = o0;
                    outF[mi][ni][hi * 2 + 1] = o1;
                    *reinterpret_cast<__nv_bfloat162*>(&sF[p * 136 + j]) =
                        __floats2bfloat162_rn(o0, o1);
                }
    }
    CP_WAIT0();
    __syncthreads();

    // ---- residual layer 1 (W in sW0; prefetch mlp2) ----
    load_w_async(5, sW1);
    gemm64(sF, sW0, acc, lane, m0, n0);
    __syncthreads();
    {
        const float* tpar = tau_params + 128;
#pragma unroll
        for (int mi = 0; mi < 2; mi++)
#pragma unroll
            for (int ni = 0; ni < 4; ni++)
#pragma unroll
                for (int hi = 0; hi < 2; hi++) {
                    int p = m0 + mi * 16 + (lane >> 2) + hi * 8;
                    int j = n0 + ni * 8 + (lane & 3) * 2;
                    float h0 = acc[mi][ni][hi * 2], h1 = acc[mi][ni][hi * 2 + 1];
                    float tp = sTau[p];
                    float tt0 = tanh_f(tp * __ldg(&tpar[j]));
                    float tt1 = tanh_f(tp * __ldg(&tpar[j + 1]));
                    float o0 = outF[mi][ni][hi * 2]     + tt0 * silu_f(h0);
                    float o1 = outF[mi][ni][hi * 2 + 1] + tt1 * silu_f(h1);
                    outF[mi][ni][hi * 2]     = o0;
                    outF[mi][ni][hi * 2 + 1] = o1;
                    *reinterpret_cast<__nv_bfloat162*>(&sF[p * 136 + j]) =
                        __floats2bfloat162_rn(o0, o1);
                }
    }
    CP_WAIT0();
    __syncthreads();

    // ---- residual layer 2 (W in sW1) — epilogue writes fp32 head staging ----
    gemm64(sF, sW1, acc, lane, m0, n0);
    __syncthreads();   // all reads of sF and sW0-free guaranteed
    {
        const float* tpar = tau_params + 256;
#pragma unroll
        for (int mi = 0; mi < 2; mi++)
#pragma unroll
            for (int ni = 0; ni < 4; ni++)
#pragma unroll
                for (int hi = 0; hi < 2; hi++) {
                    int p = m0 + mi * 16 + (lane >> 2) + hi * 8;
                    int j = n0 + ni * 8 + (lane & 3) * 2;
                    float h0 = acc[mi][ni][hi * 2], h1 = acc[mi][ni][hi * 2 + 1];
                    float tp = sTau[p];
                    float tt0 = tanh_f(tp * __ldg(&tpar[j]));
                    float tt1 = tanh_f(tp * __ldg(&tpar[j + 1]));
                    float o0 = outF[mi][ni][hi * 2]     + tt0 * silu_f(h0);
                    float o1 = outF[mi][ni][hi * 2 + 1] + tt1 * silu_f(h1);
                    *reinterpret_cast<float2*>(&sOutF[p * 132 + j]) = make_float2(o0, o1);
                }
    }
    __syncthreads();

    // ---- head: res = phys + out @ last_w^T ----
    if (tid < BP) {
        int p = tid;
        float a0 = 0.f, a1 = 0.f, a2 = 0.f;
#pragma unroll 8
        for (int j = 0; j < 128; j += 4) {
            float4 o  = *reinterpret_cast<float4*>(&sOutF[p * 132 + j]);
            float4 w0 = __ldg(reinterpret_cast<const float4*>(last_w + j));
            float4 w1 = __ldg(reinterpret_cast<const float4*>(last_w + 128 + j));
            float4 w2 = __ldg(reinterpret_cast<const float4*>(last_w + 256 + j));
            a0 += o.x * w0.x + o.y * w0.y + o.z * w0.z + o.w * w0.w;
            a1 += o.x * w1.x + o.y * w1.y + o.z * w1.z + o.w * w1.w;
            a2 += o.x * w2.x + o.y * w2.y + o.z * w2.z + o.w * w2.w;
        }
        long long gp = (long long)(p0 + p) * 3;
        outG[gp + 0] = phys[gp + 0] + a0;
        outG[gp + 1] = phys[gp + 1] + a1;
        outG[gp + 2] = phys[gp + 2] + a2;
    }
}

// ---------------------------------------------------------------------------
extern "C" void kernel_launch(void* const* d_in, const int* in_sizes, int n_in,
                              void* d_out, int out_size)
{
    const float* phys      = (const float*)d_in[0];
    const float* net       = (const float*)d_in[1];
    const float* tau       = (const float*)d_in[2];
    const float* vec_g[4]  = {(const float*)d_in[3], (const float*)d_in[4],
                              (const float*)d_in[5], (const float*)d_in[6]};
    const float* tau_g[4]  = {(const float*)d_in[7], (const float*)d_in[8],
                              (const float*)d_in[9], (const float*)d_in[10]};
    const float* vec_pe_w  = (const float*)d_in[11];
    const float* tau_pe_w  = (const float*)d_in[12];
    const float* tau_pe_b  = (const float*)d_in[13];
    const float* vec_scale = (const float*)d_in[14];
    const float* vec_map_w = (const float*)d_in[15];
    const float* tau_mlp_w = (const float*)d_in[16];
    const float* vec_mlp_w = (const float*)d_in[17];
    const float* tau_params= (const float*)d_in[18];
    const float* last_w    = (const float*)d_in[19];
    float* out = (float*)d_out;

    prolog_all<<<4720, 256>>>(vec_g[0], tau_g[0], vec_g[1], tau_g[1],
                              vec_g[2], tau_g[2], vec_g[3], tau_g[3],
                              vec_map_w, tau_mlp_w, vec_mlp_w);

    cudaFuncSetAttribute(fused_kernel, cudaFuncAttributeMaxDynamicSharedMemorySize, 105984);
    fused_kernel<<<8192, NTH, 105984>>>(phys, net, tau,
                                        vec_pe_w, tau_pe_w, tau_pe_b, vec_scale,
                                        tau_params, last_w, out);
}

// round 13
// speedup vs baseline: 2.1757x; 1.1454x over previous
#include <cuda_runtime.h>
#include <cuda_bf16.h>
#include <cstdint>

#define NTH 256
#define BP  64

// Combined channel-last bf16 grids: levels S=16,32,64,96, 32 channels each
// voxel offsets: 0, 4096, 36864, 299008 ; total 1183744 voxels
#define TOT_VOX 1183744
__device__ __align__(16) __nv_bfloat16 g_comb[(size_t)TOT_VOX * 32];
// 6 weight matrices pre-converted to bf16, row stride 136 (smem-ready layout)
// order: vec_map0, vec_map1, tau_mlp, vec_mlp0, vec_mlp1, vec_mlp2
__device__ __align__(16) __nv_bfloat16 g_wbf[6 * 128 * 136];

// ---------------------------------------------------------------------------
// Prolog: grid transpose (blocks 0..4623) + weight conversion (blocks 4624+)
// ---------------------------------------------------------------------------
__global__ void prolog_all(const float* __restrict__ v0, const float* __restrict__ t0,
                           const float* __restrict__ v1, const float* __restrict__ t1,
                           const float* __restrict__ v2, const float* __restrict__ t2,
                           const float* __restrict__ v3, const float* __restrict__ t3,
                           const float* __restrict__ vec_map_w,
                           const float* __restrict__ tau_mlp_w,
                           const float* __restrict__ vec_mlp_w)
{
    const int b = blockIdx.x;
    const int tid = threadIdx.x;

    if (b >= 4624) {  // weight conversion: 96 blocks * 256 threads = 6*128*32
        int i = (b - 4624) * 256 + tid;
        if (i >= 6 * 128 * 32) return;
        int mat = i >> 12;
        int r   = (i >> 5) & 127;
        int c4  = (i & 31) * 4;
        const float* src = (mat == 0) ? vec_map_w
                         : (mat == 1) ? vec_map_w + 16384
                         : (mat == 2) ? tau_mlp_w
                                      : vec_mlp_w + (mat - 3) * 16384;
        float4 f = *reinterpret_cast<const float4*>(src + r * 128 + c4);
        __nv_bfloat16* dst = g_wbf + (size_t)mat * 128 * 136 + r * 136 + c4;
        *reinterpret_cast<__nv_bfloat162*>(dst)     = __floats2bfloat162_rn(f.x, f.y);
        *reinterpret_cast<__nv_bfloat162*>(dst + 2) = __floats2bfloat162_rn(f.z, f.w);
        return;
    }

    __shared__ float tile[32][257];
    const float* vec; const float* tau; int vol; long long outBase; int vbase;
    if (b < 16)        { vec = v0; tau = t0; vol = 4096;   outBase = 0LL;           vbase = b * 256; }
    else if (b < 144)  { vec = v1; tau = t1; vol = 32768;  outBase = 4096LL * 32;   vbase = (b - 16) * 256; }
    else if (b < 1168) { vec = v2; tau = t2; vol = 262144; outBase = 36864LL * 32;  vbase = (b - 144) * 256; }
    else               { vec = v3; tau = t3; vol = 884736; outBase = 299008LL * 32; vbase = (b - 1168) * 256; }

    // float4 vectorized loads (all vols and vbase are multiples of 256)
    for (int i = tid; i < 32 * 64; i += 256) {
        int ch = i >> 6, v4 = (i & 63) * 4, v = vbase + v4;
        float4 val = make_float4(0.f, 0.f, 0.f, 0.f);
        if (v < vol) {
            const float* srcp = (ch < 16) ? vec + (size_t)ch * vol
                                          : tau + (size_t)(ch - 16) * vol;
            val = *reinterpret_cast<const float4*>(srcp + v);
        }
        tile[ch][v4 + 0] = val.x;
        tile[ch][v4 + 1] = val.y;
        tile[ch][v4 + 2] = val.z;
        tile[ch][v4 + 3] = val.w;
    }
    __syncthreads();
    __nv_bfloat16* out = g_comb + outBase;
    for (int i = tid; i < 16 * 256; i += 256) {
        int vl = i >> 4, cp = i & 15, v = vbase + vl;
        if (v < vol) {
            __nv_bfloat162 val = __floats2bfloat162_rn(tile[2 * cp][vl], tile[2 * cp + 1][vl]);
            *reinterpret_cast<__nv_bfloat162*>(out + (size_t)v * 32 + 2 * cp) = val;
        }
    }
}

// ---------------------------------------------------------------------------
// Math helpers
// ---------------------------------------------------------------------------
__device__ __forceinline__ float silu_f(float x) {
    // x * sigmoid(x) = 0.5x * (1 + tanh(0.5x)); HW tanh = 1 MUFU
    float h = 0.5f * x, t;
    asm("tanh.approx.f32 %0, %1;" : "=f"(t) : "f"(h));
    return fmaf(h, t, h);
}
__device__ __forceinline__ float tanh_f(float x) {
    float ax = fabsf(x);
    if (ax < 0.25f) {
        float x2 = x * x;
        return x * (1.f + x2 * (-0.333333333f + x2 * (0.133333333f - 0.0539682540f * x2)));
    }
    float e = __expf(2.f * x);
    return 1.f - __fdividef(2.f, e + 1.f);
}

__device__ __forceinline__ void accum8(float* acc, uint4 q, float w) {
    float2 f;
    f = __bfloat1622float2(*reinterpret_cast<__nv_bfloat162*>(&q.x));
    acc[0] = fmaf(w, f.x, acc[0]); acc[1] = fmaf(w, f.y, acc[1]);
    f = __bfloat1622float2(*reinterpret_cast<__nv_bfloat162*>(&q.y));
    acc[2] = fmaf(w, f.x, acc[2]); acc[3] = fmaf(w, f.y, acc[3]);
    f = __bfloat1622float2(*reinterpret_cast<__nv_bfloat162*>(&q.z));
    acc[4] = fmaf(w, f.x, acc[4]); acc[5] = fmaf(w, f.y, acc[5]);
    f = __bfloat1622float2(*reinterpret_cast<__nv_bfloat162*>(&q.w));
    acc[6] = fmaf(w, f.x, acc[6]); acc[7] = fmaf(w, f.y, acc[7]);
}

// Cooperative trilinear sample: 4 lanes per point, lane owns 16B chunk ck of
// each 64B voxel. ck 0,1 -> vec channels; ck 2,3 -> tau channels.
template<int S>
__device__ __forceinline__ void sample_coop(long long voxOff, int lvlBase,
                                            float cx, float cy, float cz,
                                            int pt, int ck,
                                            __nv_bfloat16* sF, __nv_bfloat16* sT)
{
    const float s1 = (float)(S - 1);
    float px = fminf(fmaxf((cx + 1.f) * 0.5f * s1, 0.f), s1);
    float py = fminf(fmaxf((cy + 1.f) * 0.5f * s1, 0.f), s1);
    float pz = fminf(fmaxf((cz + 1.f) * 0.5f * s1, 0.f), s1);
    int x0 = (int)px, y0 = (int)py, z0 = (int)pz;
    float wx = px - (float)x0, wy = py - (float)y0, wz = pz - (float)z0;
    int x1 = min(x0 + 1, S - 1), y1 = min(y0 + 1, S - 1), z1 = min(z0 + 1, S - 1);

    const __nv_bfloat16* g = g_comb + voxOff * 32 + ck * 8;
    float acc[8];
#pragma unroll
    for (int i = 0; i < 8; i++) acc[i] = 0.f;

    const int   xs[2]  = {x0, x1}, ys[2] = {y0, y1}, zs[2] = {z0, z1};
    const float wxs[2] = {1.f - wx, wx}, wys[2] = {1.f - wy, wy}, wzs[2] = {1.f - wz, wz};
#pragma unroll
    for (int a = 0; a < 2; a++)
#pragma unroll
        for (int b = 0; b < 2; b++)
#pragma unroll
            for (int c = 0; c < 2; c++) {
                float w = wzs[a] * wys[b] * wxs[c];
                uint4 q = *reinterpret_cast<const uint4*>(
                    g + (size_t)((zs[a] * S + ys[b]) * S + xs[c]) * 32);
                accum8(acc, q, w);
            }
    __nv_bfloat16* dst = (ck < 2) ? sF : sT;
    const int cb = lvlBase + (ck & 1) * 8;
#pragma unroll
    for (int c = 0; c < 8; c += 2)
        *reinterpret_cast<__nv_bfloat162*>(&dst[pt * 136 + cb + c]) =
            __floats2bfloat162_rn(silu_f(acc[c]), silu_f(acc[c + 1]));
}

// ---------------------------------------------------------------------------
// cp.async weight prefetch (global bf16 stride-136 -> smem), one commit group
// ---------------------------------------------------------------------------
__device__ __forceinline__ void load_w_async(int mat, __nv_bfloat16* sW)
{
    const uint4* src = reinterpret_cast<const uint4*>(g_wbf + (size_t)mat * 128 * 136);
    uint32_t dst = (uint32_t)__cvta_generic_to_shared(sW);
    const int tid = threadIdx.x;
#pragma unroll
    for (int i = 0; i < 8; i++)
        asm volatile("cp.async.cg.shared.global [%0], [%1], 16;\n"
                     :: "r"(dst + (tid + i * NTH) * 16), "l"(src + tid + i * NTH));
    int i8 = tid + 8 * NTH;
    if (i8 < 2176)
        asm volatile("cp.async.cg.shared.global [%0], [%1], 16;\n"
                     :: "r"(dst + i8 * 16), "l"(src + i8));
    asm volatile("cp.async.commit_group;\n");
}
#define CP_WAIT0() asm volatile("cp.async.wait_group 0;\n" ::: "memory")

// ---------------------------------------------------------------------------
// mma.sync helpers
// ---------------------------------------------------------------------------
__device__ __forceinline__ void ldm4(uint32_t& r0, uint32_t& r1, uint32_t& r2, uint32_t& r3,
                                     uint32_t addr)
{
    asm volatile("ldmatrix.sync.aligned.m8n8.x4.shared.b16 {%0,%1,%2,%3}, [%4];\n"
                 : "=r"(r0), "=r"(r1), "=r"(r2), "=r"(r3) : "r"(addr));
}
__device__ __forceinline__ void mma16816(float* c, const uint32_t* a, const uint32_t* b)
{
    asm volatile(
        "mma.sync.aligned.m16n8k16.row.col.f32.bf16.bf16.f32 "
        "{%0,%1,%2,%3},{%4,%5,%6,%7},{%8,%9},{%0,%1,%2,%3};\n"
        : "+f"(c[0]), "+f"(c[1]), "+f"(c[2]), "+f"(c[3])
        : "r"(a[0]), "r"(a[1]), "r"(a[2]), "r"(a[3]), "r"(b[0]), "r"(b[1]));
}

// C[p][j] = sum_k A[p][k] * W[j][k], 64x128x128, bf16 in / fp32 acc.
// 8 warps: warp tile 32(m) x 32(n); frag grid 2 x 4 of m16n8k16.
__device__ __forceinline__ void gemm64(const __nv_bfloat16* A, const __nv_bfloat16* W,
                                       float (&acc)[2][4][4], int lane, int m0, int n0)
{
#pragma unroll
    for (int mi = 0; mi < 2; mi++)
#pragma unroll
        for (int ni = 0; ni < 4; ni++)
#pragma unroll
            for (int t = 0; t < 4; t++) acc[mi][ni][t] = 0.f;

    uint32_t aBase = (uint32_t)__cvta_generic_to_shared(A)
                   + (uint32_t)((m0 + (lane & 15)) * 272 + (lane >> 4) * 16);
    uint32_t bBase = (uint32_t)__cvta_generic_to_shared(W)
                   + (uint32_t)((n0 + (lane & 7) + ((lane >> 4) << 3)) * 272
                                + ((lane >> 3) & 1) * 16);
#pragma unroll
    for (int k = 0; k < 8; k++) {
        uint32_t a[2][4];
        ldm4(a[0][0], a[0][1], a[0][2], a[0][3], aBase + k * 32);
        ldm4(a[1][0], a[1][1], a[1][2], a[1][3], aBase + 16 * 272 + k * 32);
        uint32_t b[4][2];
#pragma unroll
        for (int t = 0; t < 2; t++) {
            uint32_t r0, r1, r2, r3;
            ldm4(r0, r1, r2, r3, bBase + t * (16 * 272) + k * 32);
            b[2 * t][0] = r0; b[2 * t][1] = r1;
            b[2 * t + 1][0] = r2; b[2 * t + 1][1] = r3;
        }
#pragma unroll
        for (int mi = 0; mi < 2; mi++)
#pragma unroll
            for (int ni = 0; ni < 4; ni++)
                mma16816(acc[mi][ni], a[mi], b[ni]);
    }
}

// ---------------------------------------------------------------------------
// Fused main kernel: 64 points / block, 256 threads, 2 CTAs/SM,
// double-buffered cp.async weights, in-place activation buffers.
// ---------------------------------------------------------------------------
__global__ void __launch_bounds__(NTH, 2)
fused_kernel(const float* __restrict__ phys, const float* __restrict__ net,
             const float* __restrict__ tauIn,
             const float* __restrict__ vec_pe_w, const float* __restrict__ tau_pe_w,
             const float* __restrict__ tau_pe_b, const float* __restrict__ vec_scale,
             const float* __restrict__ tau_params,
             const float* __restrict__ last_w, float* __restrict__ outG)
{
    extern __shared__ char smem[];
    __nv_bfloat16* sF  = (__nv_bfloat16*)(smem);            // 17408 B
    __nv_bfloat16* sT  = (__nv_bfloat16*)(smem + 17408);    // 17408 B
    __nv_bfloat16* sW0 = (__nv_bfloat16*)(smem + 34816);    // 34816 B
    __nv_bfloat16* sW1 = (__nv_bfloat16*)(smem + 69632);    // 34816 B
    float* sTau   = (float*)(smem + 104448);                // 256 B
    float* sScale = (float*)(smem + 104704);                // 512 B
    float* sCx    = (float*)(smem + 105216);                // 256 B
    float* sCy    = (float*)(smem + 105472);                // 256 B
    float* sCz    = (float*)(smem + 105728);                // end 105984
    float* sOutF  = (float*)(smem + 34816);                 // overlays sW0 (33792 B)

    const int tid = threadIdx.x;
    const int p0  = blockIdx.x * BP;

    // prefetch W0 (overlaps gather + FFM)
    load_w_async(0, sW0);

    if (tid < BP) {
        int gp = p0 + tid;
        sCx[tid]  = net[gp * 3 + 0];
        sCy[tid]  = net[gp * 3 + 1];
        sCz[tid]  = net[gp * 3 + 2];
        sTau[tid] = tauIn[gp];
    }
    if (tid < 128) sScale[tid] = vec_scale[tid];
    __syncthreads();

    // ---- sampling: 4 lanes cooperate per point ----
    {
        int pt = tid >> 2, ck = tid & 3;
        float cx = sCx[pt], cy = sCy[pt], cz = sCz[pt];
        sample_coop<16>(0LL,      0,  cx, cy, cz, pt, ck, sF, sT);
        sample_coop<32>(4096LL,   16, cx, cy, cz, pt, ck, sF, sT);
        sample_coop<64>(36864LL,  32, cx, cy, cz, pt, ck, sF, sT);
        sample_coop<96>(299008LL, 48, cx, cy, cz, pt, ck, sF, sT);
    }
    // ---- FFM features ----
#pragma unroll 4
    for (int i = tid; i < 64 * 64; i += NTH) {
        int p = i >> 6, j = i & 63;
        float d = sCx[p] * vec_pe_w[j * 3] + sCy[p] * vec_pe_w[j * 3 + 1]
                + sCz[p] * vec_pe_w[j * 3 + 2];
        sF[p * 136 + 64 + j] = __float2bfloat16(__sinf(d));
    }
#pragma unroll 4
    for (int i = tid; i < 64 * 64; i += NTH) {
        int p = i >> 6, j = i & 63;
        float d = sCx[p] * tau_pe_w[j * 3] + sCy[p] * tau_pe_w[j * 3 + 1]
                + sCz[p] * tau_pe_w[j * 3 + 2] + tau_pe_b[j];
        sT[p * 136 + 64 + j] = __float2bfloat16(__sinf(d));
    }
    CP_WAIT0();
    __syncthreads();

    const int lane = tid & 31, wid = tid >> 5;
    const int m0 = (wid & 1) * 32, n0 = (wid >> 1) * 32;
    float acc[2][4][4];
    float outF[2][4][4];

    // ---- vec_map layer 0 (W in sW0; prefetch W1) ----
    load_w_async(1, sW1);
    gemm64(sF, sW0, acc, lane, m0, n0);
    __syncthreads();   // all A reads done
#pragma unroll
    for (int mi = 0; mi < 2; mi++)
#pragma unroll
        for (int ni = 0; ni < 4; ni++)
#pragma unroll
            for (int hi = 0; hi < 2; hi++) {
                int p = m0 + mi * 16 + (lane >> 2) + hi * 8;
                int j = n0 + ni * 8 + (lane & 3) * 2;
                *reinterpret_cast<__nv_bfloat162*>(&sF[p * 136 + j]) =
                    __floats2bfloat162_rn(silu_f(acc[mi][ni][hi * 2]),
                                          silu_f(acc[mi][ni][hi * 2 + 1]));
            }
    CP_WAIT0();
    __syncthreads();

    // ---- vec_map layer 1 + out init (W in sW1; prefetch tau_mlp) ----
    load_w_async(2, sW0);
    gemm64(sF, sW1, acc, lane, m0, n0);
    __syncthreads();
#pragma unroll
    for (int mi = 0; mi < 2; mi++)
#pragma unroll
        for (int ni = 0; ni < 4; ni++)
#pragma unroll
            for (int hi = 0; hi < 2; hi++) {
                int p = m0 + mi * 16 + (lane >> 2) + hi * 8;
                int j = n0 + ni * 8 + (lane & 3) * 2;
                float tp = sTau[p];
                float s0 = sScale[j], s1 = sScale[j + 1];
                float o0 = tanh_f(tp * s0 * silu_f(acc[mi][ni][hi * 2]));
                float o1 = tanh_f(tp * s1 * silu_f(acc[mi][ni][hi * 2 + 1]));
                outF[mi][ni][hi * 2]     = o0;
                outF[mi][ni][hi * 2 + 1] = o1;
                *reinterpret_cast<__nv_bfloat162*>(&sF[p * 136 + j]) =
                    __floats2bfloat162_rn(o0, o1);
            }
    CP_WAIT0();
    __syncthreads();

    // ---- tau path (W in sW0; prefetch mlp0) ----
    load_w_async(3, sW1);
    gemm64(sT, sW0, acc, lane, m0, n0);
    __syncthreads();
#pragma unroll
    for (int mi = 0; mi < 2; mi++)
#pragma unroll
        for (int ni = 0; ni < 4; ni++)
#pragma unroll
            for (int hi = 0; hi < 2; hi++) {
                int p = m0 + mi * 16 + (lane >> 2) + hi * 8;
                int j = n0 + ni * 8 + (lane & 3) * 2;
                *reinterpret_cast<__nv_bfloat162*>(&sT[p * 136 + j]) =
                    __floats2bfloat162_rn(acc[mi][ni][hi * 2], acc[mi][ni][hi * 2 + 1]);
            }
    CP_WAIT0();
    __syncthreads();

    // ---- residual layer 0 (W in sW1; prefetch mlp1) ----
    load_w_async(4, sW0);
    gemm64(sF, sW1, acc, lane, m0, n0);
    __syncthreads();
    {
        const float* tpar = tau_params;
#pragma unroll
        for (int mi = 0; mi < 2; mi++)
#pragma unroll
            for (int ni = 0; ni < 4; ni++)
#pragma unroll
                for (int hi = 0; hi < 2; hi++) {
                    int p = m0 + mi * 16 + (lane >> 2) + hi * 8;
                    int j = n0 + ni * 8 + (lane & 3) * 2;
                    float2 t = __bfloat1622float2(
                        *reinterpret_cast<__nv_bfloat162*>(&sT[p * 136 + j]));
                    float h0 = acc[mi][ni][hi * 2] * t.x;
                    float h1 = acc[mi][ni][hi * 2 + 1] * t.y;
                    float tp = sTau[p];
                    float tt0 = tanh_f(tp * __ldg(&tpar[j]));
                    float tt1 = tanh_f(tp * __ldg(&tpar[j + 1]));
                    float o0 = outF[mi][ni][hi * 2]     + tt0 * silu_f(h0);
                    float o1 = outF[mi][ni][hi * 2 + 1] + tt1 * silu_f(h1);
                    outF[mi][ni][hi * 2]     = o0;
                    outF[mi][ni][hi * 2 + 1] = o1;
                    *reinterpret_cast<__nv_bfloat162*>(&sF[p * 136 + j]) =
                        __floats2bfloat162_rn(o0, o1);
                }
    }
    CP_WAIT0();
    __syncthreads();

    // ---- residual layer 1 (W in sW0; prefetch mlp2) ----
    load_w_async(5, sW1);
    gemm64(sF, sW0, acc, lane, m0, n0);
    __syncthreads();
    {
        const float* tpar = tau_params + 128;
#pragma unroll
        for (int mi = 0; mi < 2; mi++)
#pragma unroll
            for (int ni = 0; ni < 4; ni++)
#pragma unroll
                for (int hi = 0; hi < 2; hi++) {
                    int p = m0 + mi * 16 + (lane >> 2) + hi * 8;
                    int j = n0 + ni * 8 + (lane & 3) * 2;
                    float h0 = acc[mi][ni][hi * 2], h1 = acc[mi][ni][hi * 2 + 1];
                    float tp = sTau[p];
                    float tt0 = tanh_f(tp * __ldg(&tpar[j]));
                    float tt1 = tanh_f(tp * __ldg(&tpar[j + 1]));
                    float o0 = outF[mi][ni][hi * 2]     + tt0 * silu_f(h0);
                    float o1 = outF[mi][ni][hi * 2 + 1] + tt1 * silu_f(h1);
                    outF[mi][ni][hi * 2]     = o0;
                    outF[mi][ni][hi * 2 + 1] = o1;
                    *reinterpret_cast<__nv_bfloat162*>(&sF[p * 136 + j]) =
                        __floats2bfloat162_rn(o0, o1);
                }
    }
    CP_WAIT0();
    __syncthreads();

    // ---- residual layer 2 (W in sW1) — epilogue writes fp32 head staging ----
    gemm64(sF, sW1, acc, lane, m0, n0);
    __syncthreads();
    {
        const float* tpar = tau_params + 256;
#pragma unroll
        for (int mi = 0; mi < 2; mi++)
#pragma unroll
            for (int ni = 0; ni < 4; ni++)
#pragma unroll
                for (int hi = 0; hi < 2; hi++) {
                    int p = m0 + mi * 16 + (lane >> 2) + hi * 8;
                    int j = n0 + ni * 8 + (lane & 3) * 2;
                    float h0 = acc[mi][ni][hi * 2], h1 = acc[mi][ni][hi * 2 + 1];
                    float tp = sTau[p];
                    float tt0 = tanh_f(tp * __ldg(&tpar[j]));
                    float tt1 = tanh_f(tp * __ldg(&tpar[j + 1]));
                    float o0 = outF[mi][ni][hi * 2]     + tt0 * silu_f(h0);
                    float o1 = outF[mi][ni][hi * 2 + 1] + tt1 * silu_f(h1);
                    *reinterpret_cast<float2*>(&sOutF[p * 132 + j]) = make_float2(o0, o1);
                }
    }
    __syncthreads();

    // ---- head: res = phys + out @ last_w^T ----
    if (tid < BP) {
        int p = tid;
        float a0 = 0.f, a1 = 0.f, a2 = 0.f;
#pragma unroll 8
        for (int j = 0; j < 128; j += 4) {
            float4 o  = *reinterpret_cast<float4*>(&sOutF[p * 132 + j]);
            float4 w0 = __ldg(reinterpret_cast<const float4*>(last_w + j));
            float4 w1 = __ldg(reinterpret_cast<const float4*>(last_w + 128 + j));
            float4 w2 = __ldg(reinterpret_cast<const float4*>(last_w + 256 + j));
            a0 += o.x * w0.x + o.y * w0.y + o.z * w0.z + o.w * w0.w;
            a1 += o.x * w1.x + o.y * w1.y + o.z * w1.z + o.w * w1.w;
            a2 += o.x * w2.x + o.y * w2.y + o.z * w2.z + o.w * w2.w;
        }
        long long gp = (long long)(p0 + p) * 3;
        outG[gp + 0] = phys[gp + 0] + a0;
        outG[gp + 1] = phys[gp + 1] + a1;
        outG[gp + 2] = phys[gp + 2] + a2;
    }
}

// ---------------------------------------------------------------------------
extern "C" void kernel_launch(void* const* d_in, const int* in_sizes, int n_in,
                              void* d_out, int out_size)
{
    const float* phys      = (const float*)d_in[0];
    const float* net       = (const float*)d_in[1];
    const float* tau       = (const float*)d_in[2];
    const float* vec_g[4]  = {(const float*)d_in[3], (const float*)d_in[4],
                              (const float*)d_in[5], (const float*)d_in[6]};
    const float* tau_g[4]  = {(const float*)d_in[7], (const float*)d_in[8],
                              (const float*)d_in[9], (const float*)d_in[10]};
    const float* vec_pe_w  = (const float*)d_in[11];
    const float* tau_pe_w  = (const float*)d_in[12];
    const float* tau_pe_b  = (const float*)d_in[13];
    const float* vec_scale = (const float*)d_in[14];
    const float* vec_map_w = (const float*)d_in[15];
    const float* tau_mlp_w = (const float*)d_in[16];
    const float* vec_mlp_w = (const float*)d_in[17];
    const float* tau_params= (const float*)d_in[18];
    const float* last_w    = (const float*)d_in[19];
    float* out = (float*)d_out;

    prolog_all<<<4720, 256>>>(vec_g[0], tau_g[0], vec_g[1], tau_g[1],
                              vec_g[2], tau_g[2], vec_g[3], tau_g[3],
                              vec_map_w, tau_mlp_w, vec_mlp_w);

    cudaFuncSetAttribute(fused_kernel, cudaFuncAttributeMaxDynamicSharedMemorySize, 105984);
    fused_kernel<<<8192, NTH, 105984>>>(phys, net, tau,
                                        vec_pe_w, tau_pe_w, tau_pe_b, vec_scale,
                                        tau_params, last_w, out);
}

// round 17
// speedup vs baseline: 2.6406x; 1.2137x over previous
#include <cuda_runtime.h>
#include <cuda_bf16.h>
#include <cstdint>

#define NTH 256
#define BP  64

// Combined channel-last bf16 grids: levels S=16,32,64,96, 32 channels each
// voxel offsets: 0, 4096, 36864, 299008 ; total 1183744 voxels
#define TOT_VOX 1183744
__device__ __align__(16) __nv_bfloat16 g_comb[(size_t)TOT_VOX * 32];
// 6 weight matrices pre-converted to bf16, row stride 136 (smem-ready layout)
// order: vec_map0, vec_map1, tau_mlp, vec_mlp0, vec_mlp1, vec_mlp2
__device__ __align__(16) __nv_bfloat16 g_wbf[6 * 128 * 136];

// ---- smem layout (bytes) ----
#define SM_F     0        // 17408
#define SM_T     17408    // 17408
#define SM_W     34816    // 34816
#define SM_TAU   69632    // 256
#define SM_SCALE 69888    // 512
#define SM_CX    70400
#define SM_CY    70656
#define SM_CZ    70912
#define SM_TOTAL 71168
#define SM_OUT   34816    // fp32 head staging overlays sW (33792 B)

// ---------------------------------------------------------------------------
// Prolog: grid transpose (blocks 0..4623) + weight conversion (blocks 4624+)
// ---------------------------------------------------------------------------
__global__ void prolog_all(const float* __restrict__ v0, const float* __restrict__ t0,
                           const float* __restrict__ v1, const float* __restrict__ t1,
                           const float* __restrict__ v2, const float* __restrict__ t2,
                           const float* __restrict__ v3, const float* __restrict__ t3,
                           const float* __restrict__ vec_map_w,
                           const float* __restrict__ tau_mlp_w,
                           const float* __restrict__ vec_mlp_w)
{
    const int b = blockIdx.x;
    const int tid = threadIdx.x;

    if (b >= 4624) {  // weight conversion: 96 blocks * 256 threads = 6*128*32
        int i = (b - 4624) * 256 + tid;
        if (i >= 6 * 128 * 32) return;
        int mat = i >> 12;
        int r   = (i >> 5) & 127;
        int c4  = (i & 31) * 4;
        const float* src = (mat == 0) ? vec_map_w
                         : (mat == 1) ? vec_map_w + 16384
                         : (mat == 2) ? tau_mlp_w
                                      : vec_mlp_w + (mat - 3) * 16384;
        float4 f = *reinterpret_cast<const float4*>(src + r * 128 + c4);
        __nv_bfloat16* dst = g_wbf + (size_t)mat * 128 * 136 + r * 136 + c4;
        *reinterpret_cast<__nv_bfloat162*>(dst)     = __floats2bfloat162_rn(f.x, f.y);
        *reinterpret_cast<__nv_bfloat162*>(dst + 2) = __floats2bfloat162_rn(f.z, f.w);
        return;
    }

    __shared__ float tile[32][257];
    const float* vec; const float* tau; int vol; long long outBase; int vbase;
    if (b < 16)        { vec = v0; tau = t0; vol = 4096;   outBase = 0LL;           vbase = b * 256; }
    else if (b < 144)  { vec = v1; tau = t1; vol = 32768;  outBase = 4096LL * 32;   vbase = (b - 16) * 256; }
    else if (b < 1168) { vec = v2; tau = t2; vol = 262144; outBase = 36864LL * 32;  vbase = (b - 144) * 256; }
    else               { vec = v3; tau = t3; vol = 884736; outBase = 299008LL * 32; vbase = (b - 1168) * 256; }

    // float4 vectorized loads (all vols and vbase are multiples of 256)
    for (int i = tid; i < 32 * 64; i += 256) {
        int ch = i >> 6, v4 = (i & 63) * 4, v = vbase + v4;
        float4 val = make_float4(0.f, 0.f, 0.f, 0.f);
        if (v < vol) {
            const float* srcp = (ch < 16) ? vec + (size_t)ch * vol
                                          : tau + (size_t)(ch - 16) * vol;
            val = *reinterpret_cast<const float4*>(srcp + v);
        }
        tile[ch][v4 + 0] = val.x;
        tile[ch][v4 + 1] = val.y;
        tile[ch][v4 + 2] = val.z;
        tile[ch][v4 + 3] = val.w;
    }
    __syncthreads();
    // vectorized write: each thread packs one full voxel (32 ch -> 64B = 4x STG.128)
    {
        int vl = tid, v = vbase + vl;
        if (v < vol) {
            __nv_bfloat16* out = g_comb + outBase + (size_t)v * 32;
#pragma unroll
            for (int c4 = 0; c4 < 4; c4++) {
                uint32_t pk[4];
#pragma unroll
                for (int k = 0; k < 4; k++) {
                    __nv_bfloat162 bb = __floats2bfloat162_rn(tile[c4 * 8 + 2 * k][vl],
                                                              tile[c4 * 8 + 2 * k + 1][vl]);
                    pk[k] = *reinterpret_cast<uint32_t*>(&bb);
                }
                *reinterpret_cast<uint4*>(out + c4 * 8) =
                    make_uint4(pk[0], pk[1], pk[2], pk[3]);
            }
        }
    }
}

// ---------------------------------------------------------------------------
// Math helpers
// ---------------------------------------------------------------------------
__device__ __forceinline__ float silu_f(float x) {
    // x * sigmoid(x) = 0.5x * (1 + tanh(0.5x)); HW tanh = 1 MUFU
    float h = 0.5f * x, t;
    asm("tanh.approx.f32 %0, %1;" : "=f"(t) : "f"(h));
    return fmaf(h, t, h);
}
__device__ __forceinline__ float tanh_f(float x) {
    float ax = fabsf(x);
    if (ax < 0.25f) {
        float x2 = x * x;
        return x * (1.f + x2 * (-0.333333333f + x2 * (0.133333333f - 0.0539682540f * x2)));
    }
    float e = __expf(2.f * x);
    return 1.f - __fdividef(2.f, e + 1.f);
}

__device__ __forceinline__ void accum8(float* acc, uint4 q, float w) {
    float2 f;
    f = __bfloat1622float2(*reinterpret_cast<__nv_bfloat162*>(&q.x));
    acc[0] = fmaf(w, f.x, acc[0]); acc[1] = fmaf(w, f.y, acc[1]);
    f = __bfloat1622float2(*reinterpret_cast<__nv_bfloat162*>(&q.y));
    acc[2] = fmaf(w, f.x, acc[2]); acc[3] = fmaf(w, f.y, acc[3]);
    f = __bfloat1622float2(*reinterpret_cast<__nv_bfloat162*>(&q.z));
    acc[4] = fmaf(w, f.x, acc[4]); acc[5] = fmaf(w, f.y, acc[5]);
    f = __bfloat1622float2(*reinterpret_cast<__nv_bfloat162*>(&q.w));
    acc[6] = fmaf(w, f.x, acc[6]); acc[7] = fmaf(w, f.y, acc[7]);
}

// Cooperative trilinear sample: 4 lanes per point, lane owns 16B chunk ck of
// each 64B voxel. ck 0,1 -> vec channels; ck 2,3 -> tau channels.
template<int S>
__device__ __forceinline__ void sample_coop(long long voxOff, int lvlBase,
                                            float cx, float cy, float cz,
                                            int pt, int ck,
                                            __nv_bfloat16* sF, __nv_bfloat16* sT)
{
    const float s1 = (float)(S - 1);
    float px = fminf(fmaxf((cx + 1.f) * 0.5f * s1, 0.f), s1);
    float py = fminf(fmaxf((cy + 1.f) * 0.5f * s1, 0.f), s1);
    float pz = fminf(fmaxf((cz + 1.f) * 0.5f * s1, 0.f), s1);
    int x0 = (int)px, y0 = (int)py, z0 = (int)pz;
    float wx = px - (float)x0, wy = py - (float)y0, wz = pz - (float)z0;
    int x1 = min(x0 + 1, S - 1), y1 = min(y0 + 1, S - 1), z1 = min(z0 + 1, S - 1);

    const __nv_bfloat16* g = g_comb + voxOff * 32 + ck * 8;
    float acc[8];
#pragma unroll
    for (int i = 0; i < 8; i++) acc[i] = 0.f;

    const int   xs[2]  = {x0, x1}, ys[2] = {y0, y1}, zs[2] = {z0, z1};
    const float wxs[2] = {1.f - wx, wx}, wys[2] = {1.f - wy, wy}, wzs[2] = {1.f - wz, wz};
#pragma unroll
    for (int a = 0; a < 2; a++)
#pragma unroll
        for (int b = 0; b < 2; b++)
#pragma unroll
            for (int c = 0; c < 2; c++) {
                float w = wzs[a] * wys[b] * wxs[c];
                uint4 q = *reinterpret_cast<const uint4*>(
                    g + (size_t)((zs[a] * S + ys[b]) * S + xs[c]) * 32);
                accum8(acc, q, w);
            }
    __nv_bfloat16* dst = (ck < 2) ? sF : sT;
    const int cb = lvlBase + (ck & 1) * 8;
#pragma unroll
    for (int c = 0; c < 8; c += 2)
        *reinterpret_cast<__nv_bfloat162*>(&dst[pt * 136 + cb + c]) =
            __floats2bfloat162_rn(silu_f(acc[c]), silu_f(acc[c + 1]));
}

// ---------------------------------------------------------------------------
// cp.async weight prefetch (global bf16 stride-136 -> smem), one commit group
// ---------------------------------------------------------------------------
__device__ __forceinline__ void load_w_async(int mat, uint32_t dst)
{
    const uint4* src = reinterpret_cast<const uint4*>(g_wbf + (size_t)mat * 128 * 136);
    const int tid = threadIdx.x;
#pragma unroll
    for (int i = 0; i < 8; i++)
        asm volatile("cp.async.cg.shared.global [%0], [%1], 16;\n"
                     :: "r"(dst + (tid + i * NTH) * 16), "l"(src + tid + i * NTH));
    int i8 = tid + 8 * NTH;
    if (i8 < 2176)
        asm volatile("cp.async.cg.shared.global [%0], [%1], 16;\n"
                     :: "r"(dst + i8 * 16), "l"(src + i8));
    asm volatile("cp.async.commit_group;\n");
}
#define CP_WAIT0() asm volatile("cp.async.wait_group 0;\n" ::: "memory")

// ---------------------------------------------------------------------------
// mma.sync helpers
// ---------------------------------------------------------------------------
__device__ __forceinline__ void ldm4(uint32_t& r0, uint32_t& r1, uint32_t& r2, uint32_t& r3,
                                     uint32_t addr)
{
    asm volatile("ldmatrix.sync.aligned.m8n8.x4.shared.b16 {%0,%1,%2,%3}, [%4];\n"
                 : "=r"(r0), "=r"(r1), "=r"(r2), "=r"(r3) : "r"(addr));
}
__device__ __forceinline__ void mma16816(float* c, const uint32_t* a, const uint32_t* b)
{
    asm volatile(
        "mma.sync.aligned.m16n8k16.row.col.f32.bf16.bf16.f32 "
        "{%0,%1,%2,%3},{%4,%5,%6,%7},{%8,%9},{%0,%1,%2,%3};\n"
        : "+f"(c[0]), "+f"(c[1]), "+f"(c[2]), "+f"(c[3])
        : "r"(a[0]), "r"(a[1]), "r"(a[2]), "r"(a[3]), "r"(b[0]), "r"(b[1]));
}

// C[p][j] = sum_k A[p][k] * W[j][k], 64x128x128, bf16 in / fp32 acc.
// 8 warps: warp tile 32(m) x 32(n); frag grid 2 x 4 of m16n8k16.
__device__ __forceinline__ void gemm64(uint32_t aSm, uint32_t wSm,
                                       float (&acc)[2][4][4], int lane, int m0, int n0)
{
#pragma unroll
    for (int mi = 0; mi < 2; mi++)
#pragma unroll
        for (int ni = 0; ni < 4; ni++)
#pragma unroll
            for (int t = 0; t < 4; t++) acc[mi][ni][t] = 0.f;

    uint32_t aBase = aSm + (uint32_t)((m0 + (lane & 15)) * 272 + (lane >> 4) * 16);
    uint32_t bBase = wSm + (uint32_t)((n0 + (lane & 7) + ((lane >> 4) << 3)) * 272
                                      + ((lane >> 3) & 1) * 16);
#pragma unroll
    for (int k = 0; k < 8; k++) {
        uint32_t a[2][4];
        ldm4(a[0][0], a[0][1], a[0][2], a[0][3], aBase + k * 32);
        ldm4(a[1][0], a[1][1], a[1][2], a[1][3], aBase + 16 * 272 + k * 32);
        uint32_t b[4][2];
#pragma unroll
        for (int t = 0; t < 2; t++) {
            uint32_t r0, r1, r2, r3;
            ldm4(r0, r1, r2, r3, bBase + t * (16 * 272) + k * 32);
            b[2 * t][0] = r0; b[2 * t][1] = r1;
            b[2 * t + 1][0] = r2; b[2 * t + 1][1] = r3;
        }
#pragma unroll
        for (int mi = 0; mi < 2; mi++)
#pragma unroll
            for (int ni = 0; ni < 4; ni++)
                mma16816(acc[mi][ni], a[mi], b[ni]);
    }
}

// ---------------------------------------------------------------------------
// Fused main kernel: 64 points / block, 256 threads, 3 CTAs/SM,
// single cp.async weight buffer, bf16 in-place residual in sF.
// ---------------------------------------------------------------------------
__global__ void __launch_bounds__(NTH, 3)
fused_kernel(const float* __restrict__ phys, const float* __restrict__ net,
             const float* __restrict__ tauIn,
             const float* __restrict__ vec_pe_w, const float* __restrict__ tau_pe_w,
             const float* __restrict__ tau_pe_b, const float* __restrict__ vec_scale,
             const float* __restrict__ tau_params,
             const float* __restrict__ last_w, float* __restrict__ outG)
{
    extern __shared__ char smem[];
    const uint32_t smb = (uint32_t)__cvta_generic_to_shared(smem);
    __nv_bfloat16* sF = (__nv_bfloat16*)(smem + SM_F);
    __nv_bfloat16* sT = (__nv_bfloat16*)(smem + SM_T);
    float* sTau   = (float*)(smem + SM_TAU);
    float* sScale = (float*)(smem + SM_SCALE);
    float* sCx    = (float*)(smem + SM_CX);
    float* sCy    = (float*)(smem + SM_CY);
    float* sCz    = (float*)(smem + SM_CZ);
    float* sOutF  = (float*)(smem + SM_OUT);

    const int tid = threadIdx.x;
    const int p0  = blockIdx.x * BP;
    const uint32_t aF = smb + SM_F, aT = smb + SM_T, aW = smb + SM_W;

    load_w_async(0, aW);   // vec_map0, overlaps gather + FFM

    if (tid < BP) {
        int gp = p0 + tid;
        sCx[tid]  = net[gp * 3 + 0];
        sCy[tid]  = net[gp * 3 + 1];
        sCz[tid]  = net[gp * 3 + 2];
        sTau[tid] = tauIn[gp];
    }
    if (tid < 128) sScale[tid] = vec_scale[tid];
    __syncthreads();

    // ---- sampling: 4 lanes cooperate per point ----
    {
        int pt = tid >> 2, ck = tid & 3;
        float cx = sCx[pt], cy = sCy[pt], cz = sCz[pt];
        sample_coop<16>(0LL,      0,  cx, cy, cz, pt, ck, sF, sT);
        sample_coop<32>(4096LL,   16, cx, cy, cz, pt, ck, sF, sT);
        sample_coop<64>(36864LL,  32, cx, cy, cz, pt, ck, sF, sT);
        sample_coop<96>(299008LL, 48, cx, cy, cz, pt, ck, sF, sT);
    }
    // ---- FFM features: thread-per-j, weights hoisted to registers ----
    {
        int j = tid & 63, quarter = tid >> 6;
        float vw0 = vec_pe_w[j * 3], vw1 = vec_pe_w[j * 3 + 1], vw2 = vec_pe_w[j * 3 + 2];
        float tw0 = tau_pe_w[j * 3], tw1 = tau_pe_w[j * 3 + 1], tw2 = tau_pe_w[j * 3 + 2];
        float tb  = tau_pe_b[j];
#pragma unroll 4
        for (int p = quarter * 16; p < quarter * 16 + 16; p++) {
            float cx = sCx[p], cy = sCy[p], cz = sCz[p];
            sF[p * 136 + 64 + j] = __float2bfloat16(__sinf(cx * vw0 + cy * vw1 + cz * vw2));
            sT[p * 136 + 64 + j] = __float2bfloat16(__sinf(cx * tw0 + cy * tw1 + cz * tw2 + tb));
        }
    }
    CP_WAIT0();
    __syncthreads();

    const int lane = tid & 31, wid = tid >> 5;
    const int m0 = (wid & 1) * 32, n0 = (wid >> 1) * 32;
    float acc[2][4][4];

    // ---- vec_map layer 0 ----
    gemm64(aF, aW, acc, lane, m0, n0);
    __syncthreads();           // gemm reads of sF and sW done
    load_w_async(1, aW);
#pragma unroll
    for (int mi = 0; mi < 2; mi++)
#pragma unroll
        for (int ni = 0; ni < 4; ni++)
#pragma unroll
            for (int hi = 0; hi < 2; hi++) {
                int p = m0 + mi * 16 + (lane >> 2) + hi * 8;
                int j = n0 + ni * 8 + (lane & 3) * 2;
                *reinterpret_cast<__nv_bfloat162*>(&sF[p * 136 + j]) =
                    __floats2bfloat162_rn(silu_f(acc[mi][ni][hi * 2]),
                                          silu_f(acc[mi][ni][hi * 2 + 1]));
            }
    CP_WAIT0();
    __syncthreads();

    // ---- vec_map layer 1 + out init: out = tanh(tau*scale*silu(h)) ----
    gemm64(aF, aW, acc, lane, m0, n0);
    __syncthreads();
    load_w_async(2, aW);
#pragma unroll
    for (int mi = 0; mi < 2; mi++)
#pragma unroll
        for (int ni = 0; ni < 4; ni++)
#pragma unroll
            for (int hi = 0; hi < 2; hi++) {
                int p = m0 + mi * 16 + (lane >> 2) + hi * 8;
                int j = n0 + ni * 8 + (lane & 3) * 2;
                float tp = sTau[p];
                float o0 = tanh_f(tp * sScale[j]     * silu_f(acc[mi][ni][hi * 2]));
                float o1 = tanh_f(tp * sScale[j + 1] * silu_f(acc[mi][ni][hi * 2 + 1]));
                *reinterpret_cast<__nv_bfloat162*>(&sF[p * 136 + j]) =
                    __floats2bfloat162_rn(o0, o1);
            }
    CP_WAIT0();
    __syncthreads();

    // ---- tau path: ttt = tauF @ tau_mlp_w^T (bf16 back into sT) ----
    gemm64(aT, aW, acc, lane, m0, n0);
    __syncthreads();
    load_w_async(3, aW);
#pragma unroll
    for (int mi = 0; mi < 2; mi++)
#pragma unroll
        for (int ni = 0; ni < 4; ni++)
#pragma unroll
            for (int hi = 0; hi < 2; hi++) {
                int p = m0 + mi * 16 + (lane >> 2) + hi * 8;
                int j = n0 + ni * 8 + (lane & 3) * 2;
                *reinterpret_cast<__nv_bfloat162*>(&sT[p * 136 + j]) =
                    __floats2bfloat162_rn(acc[mi][ni][hi * 2], acc[mi][ni][hi * 2 + 1]);
            }
    CP_WAIT0();
    __syncthreads();

    // ---- residual layer 0 (h *= ttt) ----
    gemm64(aF, aW, acc, lane, m0, n0);
    __syncthreads();
    load_w_async(4, aW);
#pragma unroll
    for (int mi = 0; mi < 2; mi++)
#pragma unroll
        for (int ni = 0; ni < 4; ni++)
#pragma unroll
            for (int hi = 0; hi < 2; hi++) {
                int p = m0 + mi * 16 + (lane >> 2) + hi * 8;
                int j = n0 + ni * 8 + (lane & 3) * 2;
                float2 t = __bfloat1622float2(
                    *reinterpret_cast<__nv_bfloat162*>(&sT[p * 136 + j]));
                float h0 = acc[mi][ni][hi * 2] * t.x;
                float h1 = acc[mi][ni][hi * 2 + 1] * t.y;
                float tp = sTau[p];
                float tt0 = tanh_f(tp * __ldg(&tau_params[j]));
                float tt1 = tanh_f(tp * __ldg(&tau_params[j + 1]));
                __nv_bfloat162* fp = reinterpret_cast<__nv_bfloat162*>(&sF[p * 136 + j]);
                float2 op = __bfloat1622float2(*fp);
                *fp = __floats2bfloat162_rn(op.x + tt0 * silu_f(h0),
                                            op.y + tt1 * silu_f(h1));
            }
    CP_WAIT0();
    __syncthreads();

    // ---- residual layer 1 ----
    gemm64(aF, aW, acc, lane, m0, n0);
    __syncthreads();
    load_w_async(5, aW);
#pragma unroll
    for (int mi = 0; mi < 2; mi++)
#pragma unroll
        for (int ni = 0; ni < 4; ni++)
#pragma unroll
            for (int hi = 0; hi < 2; hi++) {
                int p = m0 + mi * 16 + (lane >> 2) + hi * 8;
                int j = n0 + ni * 8 + (lane & 3) * 2;
                float tp = sTau[p];
                float tt0 = tanh_f(tp * __ldg(&tau_params[128 + j]));
                float tt1 = tanh_f(tp * __ldg(&tau_params[128 + j + 1]));
                __nv_bfloat162* fp = reinterpret_cast<__nv_bfloat162*>(&sF[p * 136 + j]);
                float2 op = __bfloat1622float2(*fp);
                *fp = __floats2bfloat162_rn(
                    op.x + tt0 * silu_f(acc[mi][ni][hi * 2]),
                    op.y + tt1 * silu_f(acc[mi][ni][hi * 2 + 1]));
            }
    CP_WAIT0();
    __syncthreads();

    // ---- residual layer 2 — epilogue writes fp32 head staging (overlays sW) ----
    gemm64(aF, aW, acc, lane, m0, n0);
    __syncthreads();           // all reads of sW done before overwrite
#pragma unroll
    for (int mi = 0; mi < 2; mi++)
#pragma unroll
        for (int ni = 0; ni < 4; ni++)
#pragma unroll
            for (int hi = 0; hi < 2; hi++) {
                int p = m0 + mi * 16 + (lane >> 2) + hi * 8;
                int j = n0 + ni * 8 + (lane & 3) * 2;
                float tp = sTau[p];
                float tt0 = tanh_f(tp * __ldg(&tau_params[256 + j]));
                float tt1 = tanh_f(tp * __ldg(&tau_params[256 + j + 1]));
                float2 op = __bfloat1622float2(
                    *reinterpret_cast<__nv_bfloat162*>(&sF[p * 136 + j]));
                float o0 = op.x + tt0 * silu_f(acc[mi][ni][hi * 2]);
                float o1 = op.y + tt1 * silu_f(acc[mi][ni][hi * 2 + 1]);
                *reinterpret_cast<float2*>(&sOutF[p * 132 + j]) = make_float2(o0, o1);
            }
    __syncthreads();

    // ---- head: res = phys + out @ last_w^T ----
    if (tid < BP) {
        int p = tid;
        float a0 = 0.f, a1 = 0.f, a2 = 0.f;
#pragma unroll 8
        for (int j = 0; j < 128; j += 4) {
            float4 o  = *reinterpret_cast<float4*>(&sOutF[p * 132 + j]);
            float4 w0 = __ldg(reinterpret_cast<const float4*>(last_w + j));
            float4 w1 = __ldg(reinterpret_cast<const float4*>(last_w + 128 + j));
            float4 w2 = __ldg(reinterpret_cast<const float4*>(last_w + 256 + j));
            a0 += o.x * w0.x + o.y * w0.y + o.z * w0.z + o.w * w0.w;
            a1 += o.x * w1.x + o.y * w1.y + o.z * w1.z + o.w * w1.w;
            a2 += o.x * w2.x + o.y * w2.y + o.z * w2.z + o.w * w2.w;
        }
        long long gp = (long long)(p0 + p) * 3;
        outG[gp + 0] = phys[gp + 0] + a0;
        outG[gp + 1] = phys[gp + 1] + a1;
        outG[gp + 2] = phys[gp + 2] + a2;
    }
}

// ---------------------------------------------------------------------------
extern "C" void kernel_launch(void* const* d_in, const int* in_sizes, int n_in,
                              void* d_out, int out_size)
{
    const float* phys      = (const float*)d_in[0];
    const float* net       = (const float*)d_in[1];
    const float* tau       = (const float*)d_in[2];
    const float* vec_g[4]  = {(const float*)d_in[3], (const float*)d_in[4],
                              (const float*)d_in[5], (const float*)d_in[6]};
    const float* tau_g[4]  = {(const float*)d_in[7], (const float*)d_in[8],
                              (const float*)d_in[9], (const float*)d_in[10]};
    const float* vec_pe_w  = (const float*)d_in[11];
    const float* tau_pe_w  = (const float*)d_in[12];
    const float* tau_pe_b  = (const float*)d_in[13];
    const float* vec_scale = (const float*)d_in[14];
    const float* vec_map_w = (const float*)d_in[15];
    const float* tau_mlp_w = (const float*)d_in[16];
    const float* vec_mlp_w = (const float*)d_in[17];
    const float* tau_params= (const float*)d_in[18];
    const float* last_w    = (const float*)d_in[19];
    float* out = (float*)d_out;

    prolog_all<<<4720, 256>>>(vec_g[0], tau_g[0], vec_g[1], tau_g[1],
                              vec_g[2], tau_g[2], vec_g[3], tau_g[3],
                              vec_map_w, tau_mlp_w, vec_mlp_w);

    cudaFuncSetAttribute(fused_kernel, cudaFuncAttributeMaxDynamicSharedMemorySize, SM_TOTAL);
    fused_kernel<<<8192, NTH, SM_TOTAL>>>(phys, net, tau,
                                          vec_pe_w, tau_pe_w, tau_pe_b, vec_scale,
                                          tau_params, last_w, out);
}